// round 2
// baseline (speedup 1.0000x reference)
#include <cuda_runtime.h>
#include <math.h>

// ---------------- problem constants ----------------
#define BB    1024
#define NN_   80
#define PAST_ 64
#define FUT_  16
#define CC    51     // OUTP
#define OO    50
#define HH    128    // MLP hidden
#define DM_   26
#define NEGV  -1e30f

#define DIST_OFF 16384
#define A_OFF    (16384 + 1024*6400)

// ---------------- device scratch (no allocations allowed) ----------------
__device__ float g_x[BB * NN_ * CC];      // fused features x (B,80,51)
__device__ float g_An11[64 * 64];
__device__ float g_An22[16 * 16];
__device__ float g_Atm[16 * 64];          // 1.0 where At_softmax >= 0.004
__device__ float g_theta[50 * 50];
__device__ float g_coef;                  // -0.5 / (sigmoid(s)*0.01)

// =====================================================================
// Kernel 0: graph constants (A, An11, An22, At-mask, theta, coef)
// One block, 128 threads. Also writes output A.
// =====================================================================
__global__ void k_setup(const float* __restrict__ M, const float* __restrict__ Wk,
                        const float* __restrict__ smoothing, float* __restrict__ outA)
{
    __shared__ float sM[NN_ * DM_];
    __shared__ float sA[NN_ * NN_];
    __shared__ float d1[64];
    __shared__ float d2[16];
    const int tid = threadIdx.x;

    for (int e = tid; e < NN_ * DM_; e += 128) sM[e] = M[e];
    __syncthreads();

    // A = softmax(where(strict_lower, relu(M M^T), NEG), axis=1), zeroed outside mask
    for (int p = tid; p < NN_; p += 128) {
        float mx = NEGV;
        for (int q = 0; q < p; q++) {
            float s = 0.f;
            for (int k = 0; k < DM_; k++) s += sM[p * DM_ + k] * sM[q * DM_ + k];
            s = fmaxf(s, 0.f);
            sA[p * NN_ + q] = s;
            mx = fmaxf(mx, s);
        }
        float sum = 0.f;
        for (int q = 0; q < p; q++) {
            float e = expf(sA[p * NN_ + q] - mx);
            sA[p * NN_ + q] = e;
            sum += e;
        }
        float inv = (p > 0) ? 1.f / sum : 0.f;
        for (int q = 0; q < p; q++) sA[p * NN_ + q] *= inv;
        for (int q = p; q < NN_; q++) sA[p * NN_ + q] = 0.f;
    }
    __syncthreads();

    // write output A
    for (int e = tid; e < NN_ * NN_; e += 128) outA[e] = sA[e];

    // degrees for A11 / A22
    if (tid < 64) {
        int c = 0;
        for (int q = 0; q < 64; q++) c += (sA[tid * NN_ + q] > 1e-15f) ? 1 : 0;
        d1[tid] = rsqrtf(1.f + (float)c);
    }
    if (tid < 16) {
        int p = 64 + tid;
        int c = 0;
        for (int q = 64; q < 80; q++) c += (sA[p * NN_ + q] > 1e-15f) ? 1 : 0;
        d2[tid] = rsqrtf(1.f + (float)c);
    }
    __syncthreads();

    for (int e = tid; e < 64 * 64; e += 128) {
        int p = e >> 6, q = e & 63;
        g_An11[e] = d1[p] * sA[p * NN_ + q] * d1[q];
    }
    for (int e = tid; e < 256; e += 128) {
        int p = e >> 4, q = e & 15;
        g_An22[e] = d2[p] * sA[(64 + p) * NN_ + 64 + q] * d2[q];
    }

    // At = softmax(where(A[64:, :64] != 0, ., NEG), axis=1); mask >= 0.004
    if (tid < 16) {
        int p = 64 + tid;
        float mx = NEGV;
        for (int i = 0; i < 64; i++) {
            float a = sA[p * NN_ + i];
            float l = (a != 0.f) ? a : NEGV;
            mx = fmaxf(mx, l);
        }
        float sum = 0.f;
        for (int i = 0; i < 64; i++) {
            float a = sA[p * NN_ + i];
            float l = (a != 0.f) ? a : NEGV;
            sum += expf(l - mx);
        }
        float inv = 1.f / sum;
        for (int i = 0; i < 64; i++) {
            float a = sA[p * NN_ + i];
            float l = (a != 0.f) ? a : NEGV;
            float v = expf(l - mx) * inv;
            g_Atm[tid * 64 + i] = (v >= 0.004f) ? 1.f : 0.f;
        }
    }

    // theta = Wk @ Wk^T  (symmetric; (t+t^T)/2 is identity here)
    for (int e = tid; e < 50 * 50; e += 128) {
        int p = e / 50, q = e % 50;
        float s = 0.f;
        for (int k = 0; k < 64; k++) s += Wk[p * 64 + k] * Wk[q * 64 + k];
        g_theta[e] = s;
    }

    if (tid == 0) {
        float sg = 1.f / (1.f + expf(-smoothing[0]));
        g_coef = -0.5f / (sg * 0.01f);
    }
}

// =====================================================================
// Kernel 1: fused embedding gather + 3-layer MLP (token GEMM)
// 256 threads, 128 tokens/block, 640 blocks. 8x8 register tiles.
// =====================================================================
#define PA 133
__global__ void __launch_bounds__(256) k_mlp(
    const float* __restrict__ data,
    const float* __restrict__ emb0, const float* __restrict__ emb1, const float* __restrict__ emb2,
    const float* __restrict__ w1, const float* __restrict__ b1,
    const float* __restrict__ w2, const float* __restrict__ b2,
    const float* __restrict__ w3, const float* __restrict__ b3)
{
    extern __shared__ float sh[];
    float* bufA  = sh;                 // 128*PA
    float* bufB  = sh + 128 * PA;      // 128*PA
    float* sb1   = sh + 2 * 128 * PA;  // 128
    float* sb2   = sb1 + 128;          // 128
    float* sb3   = sb2 + 128;          // 64
    float* sLast = sb3 + 64;           // 128

    const int tid = threadIdx.x;
    const int tx = tid & 15, ty = tid >> 4;
    const int base = blockIdx.x * 128;

    for (int e = tid; e < 128; e += 256) { sb1[e] = b1[e]; sb2[e] = b2[e]; }
    for (int e = tid; e < 64; e += 256) sb3[e] = (e < 50) ? b3[e] : 0.f;
    for (int e = tid; e < 128; e += 256) sLast[e] = data[(size_t)(base + e) * 6 + 5];

    // gather X tile (128 x 51): [emb0(32), emb1(8), emb2(8), data[3:6](3)]
    for (int e = tid; e < 128 * 51; e += 256) {
        int t = e / 51, c = e % 51;
        const float* dr = data + (size_t)(base + t) * 6;
        float v;
        if (c < 32)      { int i0 = (int)dr[0]; v = emb0[i0 * 32 + c]; }
        else if (c < 40) { int i1 = (int)dr[1]; v = emb1[i1 * 8 + (c - 32)]; }
        else if (c < 48) { int i2 = (int)dr[2]; v = emb2[i2 * 8 + (c - 40)]; }
        else             { v = dr[3 + (c - 48)]; }
        bufA[t * PA + c] = v;
    }
    // W1 -> bufB
    for (int e = tid; e < 128 * 51; e += 256) {
        int o = e / 51, k = e % 51;
        bufB[o * PA + k] = w1[e];
    }
    __syncthreads();

    // -------- GEMM1: h1 = relu(X @ W1^T + b1) -> bufB --------
    {
        float acc[8][8];
        #pragma unroll
        for (int i = 0; i < 8; i++)
            #pragma unroll
            for (int j = 0; j < 8; j++) acc[i][j] = 0.f;
        for (int k = 0; k < 51; k++) {
            float a[8], b[8];
            #pragma unroll
            for (int i = 0; i < 8; i++) a[i] = bufA[(ty + 16 * i) * PA + k];
            #pragma unroll
            for (int j = 0; j < 8; j++) b[j] = bufB[(tx + 16 * j) * PA + k];
            #pragma unroll
            for (int i = 0; i < 8; i++)
                #pragma unroll
                for (int j = 0; j < 8; j++) acc[i][j] = fmaf(a[i], b[j], acc[i][j]);
        }
        __syncthreads();
        #pragma unroll
        for (int i = 0; i < 8; i++)
            #pragma unroll
            for (int j = 0; j < 8; j++) {
                int r = ty + 16 * i, c = tx + 16 * j;
                bufB[r * PA + c] = fmaxf(acc[i][j] + sb1[c], 0.f);
            }
        __syncthreads();
    }
    // W2 -> bufA (over X)
    for (int e = tid; e < 128 * 128; e += 256) {
        int o = e >> 7, k = e & 127;
        bufA[o * PA + k] = w2[e];
    }
    __syncthreads();

    // -------- GEMM2: h2 = relu(h1 @ W2^T + b2) -> bufA --------
    {
        float acc[8][8];
        #pragma unroll
        for (int i = 0; i < 8; i++)
            #pragma unroll
            for (int j = 0; j < 8; j++) acc[i][j] = 0.f;
        for (int k = 0; k < 128; k++) {
            float a[8], b[8];
            #pragma unroll
            for (int i = 0; i < 8; i++) a[i] = bufB[(ty + 16 * i) * PA + k];
            #pragma unroll
            for (int j = 0; j < 8; j++) b[j] = bufA[(tx + 16 * j) * PA + k];
            #pragma unroll
            for (int i = 0; i < 8; i++)
                #pragma unroll
                for (int j = 0; j < 8; j++) acc[i][j] = fmaf(a[i], b[j], acc[i][j]);
        }
        __syncthreads();
        #pragma unroll
        for (int i = 0; i < 8; i++)
            #pragma unroll
            for (int j = 0; j < 8; j++) {
                int r = ty + 16 * i, c = tx + 16 * j;
                bufA[r * PA + c] = fmaxf(acc[i][j] + sb2[c], 0.f);
            }
        __syncthreads();
    }
    // W3 -> bufB rows 0..63 (rows >=50 zero)
    for (int e = tid; e < 64 * 128; e += 256) {
        int o = e >> 7, k = e & 127;
        bufB[o * PA + k] = (o < 50) ? w3[o * 128 + k] : 0.f;
    }
    __syncthreads();

    // -------- GEMM3: h3 = h2 @ W3^T + b3 -> g_x --------
    {
        float acc[8][4];
        #pragma unroll
        for (int i = 0; i < 8; i++)
            #pragma unroll
            for (int j = 0; j < 4; j++) acc[i][j] = 0.f;
        for (int k = 0; k < 128; k++) {
            float a[8], b[4];
            #pragma unroll
            for (int i = 0; i < 8; i++) a[i] = bufA[(ty + 16 * i) * PA + k];
            #pragma unroll
            for (int j = 0; j < 4; j++) b[j] = bufB[(tx + 16 * j) * PA + k];
            #pragma unroll
            for (int i = 0; i < 8; i++)
                #pragma unroll
                for (int j = 0; j < 4; j++) acc[i][j] = fmaf(a[i], b[j], acc[i][j]);
        }
        #pragma unroll
        for (int i = 0; i < 8; i++)
            #pragma unroll
            for (int j = 0; j < 4; j++) {
                int c = tx + 16 * j;
                if (c < 50) {
                    int r = ty + 16 * i;
                    g_x[(size_t)(base + r) * CC + c] = acc[i][j] + sb3[c];
                }
            }
        for (int e = tid; e < 128; e += 256)
            g_x[(size_t)(base + e) * CC + 50] = sLast[e];
    }
}

// =====================================================================
// Kernel 2: per-graph pipeline (gcnn1, theta attention, gcnn2, dist)
// One block per batch element, 256 threads.
// =====================================================================
#define PX 53
#define PZ 65

__device__ __forceinline__ void gemm64_NT(const float* __restrict__ Aact, int pa,
                                          const float* __restrict__ Wt, int pw,
                                          int K, float* __restrict__ C, bool do_relu,
                                          int tx, int ty)
{
    float acc[4][4];
    #pragma unroll
    for (int i = 0; i < 4; i++)
        #pragma unroll
        for (int j = 0; j < 4; j++) acc[i][j] = 0.f;
    for (int k = 0; k < K; k++) {
        float a[4], b[4];
        #pragma unroll
        for (int i = 0; i < 4; i++) a[i] = Aact[(ty + 16 * i) * pa + k];
        #pragma unroll
        for (int j = 0; j < 4; j++) b[j] = Wt[(tx + 16 * j) * pw + k];
        #pragma unroll
        for (int i = 0; i < 4; i++)
            #pragma unroll
            for (int j = 0; j < 4; j++) acc[i][j] = fmaf(a[i], b[j], acc[i][j]);
    }
    __syncthreads();
    #pragma unroll
    for (int i = 0; i < 4; i++)
        #pragma unroll
        for (int j = 0; j < 4; j++) {
            float v = acc[i][j];
            if (do_relu) v = fmaxf(v, 0.f);
            C[(ty + 16 * i) * PZ + tx + 16 * j] = v;
        }
    __syncthreads();
}

__device__ __forceinline__ void gemm64_NN(const float* __restrict__ Ar, int pa,
                                          const float* __restrict__ Z, int K,
                                          float* __restrict__ C, bool do_relu,
                                          int tx, int ty)
{
    float acc[4][4];
    #pragma unroll
    for (int i = 0; i < 4; i++)
        #pragma unroll
        for (int j = 0; j < 4; j++) acc[i][j] = 0.f;
    for (int k = 0; k < K; k++) {
        float a[4], b[4];
        #pragma unroll
        for (int i = 0; i < 4; i++) a[i] = Ar[(ty + 16 * i) * pa + k];
        #pragma unroll
        for (int j = 0; j < 4; j++) b[j] = Z[k * PZ + tx + 16 * j];
        #pragma unroll
        for (int i = 0; i < 4; i++)
            #pragma unroll
            for (int j = 0; j < 4; j++) acc[i][j] = fmaf(a[i], b[j], acc[i][j]);
    }
    __syncthreads();
    #pragma unroll
    for (int i = 0; i < 4; i++)
        #pragma unroll
        for (int j = 0; j < 4; j++) {
            float v = acc[i][j];
            if (do_relu) v = fmaxf(v, 0.f);
            C[(ty + 16 * i) * PZ + tx + 16 * j] = v;
        }
    __syncthreads();
}

__global__ void __launch_bounds__(256) k_main(
    const float* __restrict__ Wg1a, const float* __restrict__ Wg1b,
    const float* __restrict__ Wg2a, const float* __restrict__ Wg2b,
    float* __restrict__ dout)
{
    extern __shared__ float sh[];
    float* xs    = sh;                    // 80*PX
    float* Wa1   = xs + 80 * PX;          // 64*PX
    float* Wa2   = Wa1 + 64 * PX;         // 64*PX
    float* Wb1   = Wa2 + 64 * PX;         // 64*PZ
    float* An11s = Wb1 + 64 * PZ;         // 64*PZ
    float* zb1   = An11s + 64 * PZ;       // 64*PZ
    float* zb2   = zb1 + 64 * PZ;         // 64*PZ
    float* ths   = zb2 + 64 * PZ;         // 50*PZ
    float* z3    = ths + 50 * PZ;         // 16*PZ
    float* t2b   = z3 + 16 * PZ;          // 16*PZ
    float* Ls    = t2b + 16 * PZ;         // 16*PZ
    float* An22s = Ls + 16 * PZ;          // 16*17
    float* Atms  = An22s + 16 * 17;       // 1024
    float* Wg2bs = Atms + 1024;           // 64
    float* yhv   = Wg2bs + 64;            // 16
    float* z4v   = yhv + 16;              // 16
    float* sqv   = z4v + 16;              // 80

    const int tid = threadIdx.x;
    const int tx = tid & 15, ty = tid >> 4;
    const int b = blockIdx.x;
    const float* gx = g_x + (size_t)b * NN_ * CC;

    // -------- load phase --------
    for (int e = tid; e < 80 * 51; e += 256) xs[(e / 51) * PX + e % 51] = gx[e];
    for (int e = tid; e < 64 * 51; e += 256) Wa1[(e / 51) * PX + e % 51] = Wg1a[e];
    for (int e = tid; e < 64 * 51; e += 256) Wa2[(e / 51) * PX + e % 51] = Wg2a[e];
    for (int e = tid; e < 64 * 64; e += 256) {
        int o = e >> 6, k = e & 63;
        Wb1[o * PZ + k] = (o < 50) ? Wg1b[o * 64 + k] : 0.f;
    }
    for (int e = tid; e < 64 * 64; e += 256) An11s[(e >> 6) * PZ + (e & 63)] = g_An11[e];
    for (int e = tid; e < 50 * 64; e += 256) {
        int p = e >> 6, q = e & 63;
        ths[p * PZ + q] = (q < 50) ? g_theta[p * 50 + q] : 0.f;
    }
    for (int e = tid; e < 256; e += 256) An22s[(e >> 4) * 17 + (e & 15)] = g_An22[e];
    for (int e = tid; e < 1024; e += 256) Atms[e] = g_Atm[e];
    for (int e = tid; e < 64; e += 256) Wg2bs[e] = Wg2b[e];
    __syncthreads();

    // -------- gcnn1 --------
    gemm64_NT(xs, PX, Wa1, PX, 51, zb1, false, tx, ty);   // z1 = sg1 @ Wg1a^T
    gemm64_NN(An11s, PZ, zb1, 64, zb2, true, tx, ty);     // t1 = relu(An11 @ z1)
    gemm64_NT(zb2, PZ, Wb1, PZ, 64, zb1, false, tx, ty);  // z2 = t1 @ Wg1b^T (cols>=50 zero)
    gemm64_NN(An11s, PZ, zb1, 64, zb2, false, tx, ty);    // x1 = An11 @ z2  -> zb2
    gemm64_NN(zb2, PZ, ths, 50, zb1, false, tx, ty);      // u  = x1 @ theta -> zb1

    // -------- V = xf @ theta (16x64, cols>=50 zero) -> z3 --------
    {
        float acc[4] = {0.f, 0.f, 0.f, 0.f};
        for (int k = 0; k < 50; k++) {
            float a = xs[(64 + ty) * PX + k];
            #pragma unroll
            for (int j = 0; j < 4; j++) acc[j] = fmaf(a, ths[k * PZ + tx + 16 * j], acc[j]);
        }
        __syncthreads();
        #pragma unroll
        for (int j = 0; j < 4; j++) z3[ty * PZ + tx + 16 * j] = acc[j];
        __syncthreads();
    }

    // -------- q[j][i] = (xp_i - xf_j) . (u_i - v_j); masked logits -> Ls --------
    {
        float cf = g_coef;
        float acc[4] = {0.f, 0.f, 0.f, 0.f};
        for (int k = 0; k < 50; k++) {
            float xfk = xs[(64 + ty) * PX + k];
            float vk  = z3[ty * PZ + k];
            #pragma unroll
            for (int j = 0; j < 4; j++) {
                int i = tx + 16 * j;
                acc[j] = fmaf(zb2[i * PZ + k] - xfk, zb1[i * PZ + k] - vk, acc[j]);
            }
        }
        __syncthreads();
        #pragma unroll
        for (int j = 0; j < 4; j++) {
            int i = tx + 16 * j;
            float lg = cf * acc[j];
            Ls[ty * PZ + i] = (Atms[ty * 64 + i] != 0.f) ? lg : NEGV;
        }
        __syncthreads();
    }

    // -------- softmax over j (per past index i) --------
    if (tid < 64) {
        int i = tid;
        float m = NEGV;
        for (int j = 0; j < 16; j++) m = fmaxf(m, Ls[j * PZ + i]);
        float s = 0.f;
        for (int j = 0; j < 16; j++) {
            float e = expf(Ls[j * PZ + i] - m);
            Ls[j * PZ + i] = e;
            s += e;
        }
        float inv = 1.f / s;
        for (int j = 0; j < 16; j++) Ls[j * PZ + i] *= inv;
    }
    __syncthreads();

    // -------- yh[j] = sum_i alpha[j][i] * y[i]; splice into xs --------
    if (tid < 16) {
        float s = 0.f;
        for (int i = 0; i < 64; i++) s = fmaf(Ls[tid * PZ + i], xs[i * PX + 50], s);
        yhv[tid] = s;
    }
    __syncthreads();
    if (tid < 16) xs[(64 + tid) * PX + 50] = yhv[tid];
    __syncthreads();

    // -------- gcnn2 --------
    { // z3g = x2 @ Wg2a^T (16x64)
        float acc[4] = {0.f, 0.f, 0.f, 0.f};
        for (int k = 0; k < 51; k++) {
            float a = xs[(64 + ty) * PX + k];
            #pragma unroll
            for (int j = 0; j < 4; j++) acc[j] = fmaf(a, Wa2[(tx + 16 * j) * PX + k], acc[j]);
        }
        __syncthreads();
        #pragma unroll
        for (int j = 0; j < 4; j++) z3[ty * PZ + tx + 16 * j] = acc[j];
        __syncthreads();
    }
    { // t2 = relu(An22 @ z3g)
        float acc[4] = {0.f, 0.f, 0.f, 0.f};
        for (int q = 0; q < 16; q++) {
            float a = An22s[ty * 17 + q];
            #pragma unroll
            for (int j = 0; j < 4; j++) acc[j] = fmaf(a, z3[q * PZ + tx + 16 * j], acc[j]);
        }
        __syncthreads();
        #pragma unroll
        for (int j = 0; j < 4; j++) t2b[ty * PZ + tx + 16 * j] = fmaxf(acc[j], 0.f);
        __syncthreads();
    }
    if (tid < 16) {
        float s = 0.f;
        for (int c = 0; c < 64; c++) s = fmaf(t2b[tid * PZ + c], Wg2bs[c], s);
        z4v[tid] = s;
    }
    __syncthreads();
    if (tid < 16) {
        float s = 0.f;
        for (int q = 0; q < 16; q++) s = fmaf(An22s[tid * 17 + q], z4v[q], s);
        dout[b * 16 + tid] = s;
    }

    // -------- pairwise dist on xc (80x51) --------
    if (tid < 80) {
        float s = 0.f;
        for (int c = 0; c < 51; c++) {
            float v = xs[tid * PX + c];
            s = fmaf(v, v, s);
        }
        sqv[tid] = s;
    }
    __syncthreads();
    {
        float acc[5][5];
        #pragma unroll
        for (int i = 0; i < 5; i++)
            #pragma unroll
            for (int j = 0; j < 5; j++) acc[i][j] = 0.f;
        for (int k = 0; k < 51; k++) {
            float a[5], bb[5];
            #pragma unroll
            for (int i = 0; i < 5; i++) a[i] = xs[(ty * 5 + i) * PX + k];
            #pragma unroll
            for (int j = 0; j < 5; j++) bb[j] = xs[(tx * 5 + j) * PX + k];
            #pragma unroll
            for (int i = 0; i < 5; i++)
                #pragma unroll
                for (int j = 0; j < 5; j++) acc[i][j] = fmaf(a[i], bb[j], acc[i][j]);
        }
        float* dd = dout + DIST_OFF + (size_t)b * 6400;
        #pragma unroll
        for (int i = 0; i < 5; i++)
            #pragma unroll
            for (int j = 0; j < 5; j++) {
                int n = ty * 5 + i, m = tx * 5 + j;
                float d2 = sqv[n] + sqv[m] - 2.f * acc[i][j];
                dd[n * 80 + m] = (d2 > 0.f) ? sqrtf(d2) : 0.f;
            }
    }
}

// =====================================================================
// launcher
// =====================================================================
extern "C" void kernel_launch(void* const* d_in, const int* in_sizes, int n_in,
                              void* d_out, int out_size)
{
    const float* data  = (const float*)d_in[0];
    const float* emb0  = (const float*)d_in[1];
    const float* emb1  = (const float*)d_in[2];
    const float* emb2  = (const float*)d_in[3];
    const float* w1    = (const float*)d_in[4];
    const float* b1    = (const float*)d_in[5];
    const float* w2    = (const float*)d_in[6];
    const float* b2    = (const float*)d_in[7];
    const float* w3    = (const float*)d_in[8];
    const float* b3    = (const float*)d_in[9];
    const float* M     = (const float*)d_in[10];
    const float* Wg1a  = (const float*)d_in[11];
    const float* Wg1b  = (const float*)d_in[12];
    const float* Wk    = (const float*)d_in[13];
    const float* smoothing = (const float*)d_in[14];
    const float* Wg2a  = (const float*)d_in[15];
    const float* Wg2b  = (const float*)d_in[16];
    float* out = (float*)d_out;

    const int SMEM_MLP  = (2 * 128 * PA + 128 + 128 + 64 + 128) * 4;
    const int SMEM_MAIN = (80 * PX + 2 * 64 * PX + 4 * 64 * PZ + 50 * PZ +
                           3 * 16 * PZ + 16 * 17 + 1024 + 64 + 16 + 16 + 80) * 4;

    cudaFuncSetAttribute(k_mlp, cudaFuncAttributeMaxDynamicSharedMemorySize, SMEM_MLP);
    cudaFuncSetAttribute(k_main, cudaFuncAttributeMaxDynamicSharedMemorySize, SMEM_MAIN);

    k_setup<<<1, 128>>>(M, Wk, smoothing, out + A_OFF);
    k_mlp<<<640, 256, SMEM_MLP>>>(data, emb0, emb1, emb2, w1, b1, w2, b2, w3, b3);
    k_main<<<1024, 256, SMEM_MAIN>>>(Wg1a, Wg1b, Wg2a, Wg2b, out);
}

// round 3
// speedup vs baseline: 1.1757x; 1.1757x over previous
#include <cuda_runtime.h>
#include <math.h>

// ---------------- problem constants ----------------
#define BB    1024
#define NN_   80
#define PAST_ 64
#define FUT_  16
#define CC    51     // OUTP
#define OO    50
#define HH    128    // MLP hidden
#define DM_   26
#define NEGV  -1e30f

#define DIST_OFF 16384
#define A_OFF    (16384 + 1024*6400)

// ---------------- device scratch (no allocations allowed) ----------------
__device__ float g_x[BB * NN_ * CC];      // fused features x (B,80,51)
__device__ float g_An11[64 * 64];
__device__ float g_An22[16 * 16];
__device__ unsigned int g_AtmBits[32];    // 16 rows x 64 bits (At_softmax >= 0.004)
__device__ float g_theta[50 * 50];
__device__ float g_coef;                  // -0.5 / (sigmoid(s)*0.01)

// =====================================================================
// Kernel 0: graph constants. 1 block x 1024 threads, warp-parallel rows.
// =====================================================================
__global__ void __launch_bounds__(1024) k_setup(
    const float* __restrict__ M, const float* __restrict__ Wk,
    const float* __restrict__ smoothing, float* __restrict__ outA)
{
    __shared__ float sM[NN_ * DM_];
    __shared__ float sA[NN_ * NN_];
    __shared__ float d1[64];
    __shared__ float d2[16];
    const int tid = threadIdx.x;
    const int lane = tid & 31, warp = tid >> 5;

    for (int e = tid; e < NN_ * DM_; e += 1024) sM[e] = M[e];
    for (int e = tid; e < NN_ * NN_; e += 1024) sA[e] = 0.f;
    __syncthreads();

    // A = softmax(where(strict_lower, relu(M M^T), NEG)) — one warp per row
    for (int p = warp; p < NN_; p += 32) {
        float vals[3];
        float mx = NEGV;
        int cnt = 0;
        for (int q = lane; q < p; q += 32) {
            float s = 0.f;
            #pragma unroll
            for (int k = 0; k < DM_; k++) s = fmaf(sM[p * DM_ + k], sM[q * DM_ + k], s);
            s = fmaxf(s, 0.f);
            vals[cnt++] = s;
            mx = fmaxf(mx, s);
        }
        #pragma unroll
        for (int off = 16; off; off >>= 1) mx = fmaxf(mx, __shfl_xor_sync(0xffffffffu, mx, off));
        float sum = 0.f;
        for (int c = 0; c < cnt; c++) { vals[c] = expf(vals[c] - mx); sum += vals[c]; }
        #pragma unroll
        for (int off = 16; off; off >>= 1) sum += __shfl_xor_sync(0xffffffffu, sum, off);
        float inv = (p > 0) ? 1.f / sum : 0.f;
        cnt = 0;
        for (int q = lane; q < p; q += 32) sA[p * NN_ + q] = vals[cnt++] * inv;
    }
    __syncthreads();

    // write output A
    for (int e = tid; e < NN_ * NN_; e += 1024) outA[e] = sA[e];

    // degrees
    if (tid < 64) {
        int c = 0;
        for (int q = 0; q < 64; q++) c += (sA[tid * NN_ + q] > 1e-15f) ? 1 : 0;
        d1[tid] = rsqrtf(1.f + (float)c);
    } else if (tid < 80) {
        int p = tid; // rows 64..79
        int c = 0;
        for (int q = 64; q < 80; q++) c += (sA[p * NN_ + q] > 1e-15f) ? 1 : 0;
        d2[tid - 64] = rsqrtf(1.f + (float)c);
    }
    __syncthreads();

    for (int e = tid; e < 64 * 64; e += 1024) {
        int p = e >> 6, q = e & 63;
        g_An11[e] = d1[p] * sA[p * NN_ + q] * d1[q];
    }
    if (tid < 256) {
        int p = tid >> 4, q = tid & 15;
        g_An22[tid] = d2[p] * sA[(64 + p) * NN_ + 64 + q] * d2[q];
    }

    // At softmax mask bits
    if (tid < 16) {
        int p = 64 + tid;
        float mx = NEGV;
        for (int i = 0; i < 64; i++) {
            float a = sA[p * NN_ + i];
            float l = (a != 0.f) ? a : NEGV;
            mx = fmaxf(mx, l);
        }
        float sum = 0.f;
        for (int i = 0; i < 64; i++) {
            float a = sA[p * NN_ + i];
            float l = (a != 0.f) ? a : NEGV;
            sum += expf(l - mx);
        }
        float inv = 1.f / sum;
        unsigned int b0 = 0u, b1 = 0u;
        for (int i = 0; i < 64; i++) {
            float a = sA[p * NN_ + i];
            float l = (a != 0.f) ? a : NEGV;
            float v = expf(l - mx) * inv;
            if (v >= 0.004f) {
                if (i < 32) b0 |= (1u << i);
                else        b1 |= (1u << (i - 32));
            }
        }
        g_AtmBits[tid * 2]     = b0;
        g_AtmBits[tid * 2 + 1] = b1;
    }

    // theta = Wk @ Wk^T
    for (int e = tid; e < 50 * 50; e += 1024) {
        int p = e / 50, q = e % 50;
        float s = 0.f;
        #pragma unroll 8
        for (int k = 0; k < 64; k++) s = fmaf(Wk[p * 64 + k], Wk[q * 64 + k], s);
        g_theta[e] = s;
    }

    if (tid == 0) {
        float sg = 1.f / (1.f + expf(-smoothing[0]));
        g_coef = -0.5f / (sg * 0.01f);
    }
}

// =====================================================================
// Kernel 1: fused embedding gather + 3-layer MLP (unchanged this round)
// =====================================================================
#define PA 133
__global__ void __launch_bounds__(256) k_mlp(
    const float* __restrict__ data,
    const float* __restrict__ emb0, const float* __restrict__ emb1, const float* __restrict__ emb2,
    const float* __restrict__ w1, const float* __restrict__ b1,
    const float* __restrict__ w2, const float* __restrict__ b2,
    const float* __restrict__ w3, const float* __restrict__ b3)
{
    extern __shared__ float sh[];
    float* bufA  = sh;                 // 128*PA
    float* bufB  = sh + 128 * PA;      // 128*PA
    float* sb1   = sh + 2 * 128 * PA;  // 128
    float* sb2   = sb1 + 128;          // 128
    float* sb3   = sb2 + 128;          // 64
    float* sLast = sb3 + 64;           // 128

    const int tid = threadIdx.x;
    const int tx = tid & 15, ty = tid >> 4;
    const int base = blockIdx.x * 128;

    for (int e = tid; e < 128; e += 256) { sb1[e] = b1[e]; sb2[e] = b2[e]; }
    for (int e = tid; e < 64; e += 256) sb3[e] = (e < 50) ? b3[e] : 0.f;
    for (int e = tid; e < 128; e += 256) sLast[e] = data[(size_t)(base + e) * 6 + 5];

    for (int e = tid; e < 128 * 51; e += 256) {
        int t = e / 51, c = e % 51;
        const float* dr = data + (size_t)(base + t) * 6;
        float v;
        if (c < 32)      { int i0 = (int)dr[0]; v = emb0[i0 * 32 + c]; }
        else if (c < 40) { int i1 = (int)dr[1]; v = emb1[i1 * 8 + (c - 32)]; }
        else if (c < 48) { int i2 = (int)dr[2]; v = emb2[i2 * 8 + (c - 40)]; }
        else             { v = dr[3 + (c - 48)]; }
        bufA[t * PA + c] = v;
    }
    for (int e = tid; e < 128 * 51; e += 256) {
        int o = e / 51, k = e % 51;
        bufB[o * PA + k] = w1[e];
    }
    __syncthreads();

    // GEMM1: h1 = relu(X @ W1^T + b1) -> bufB
    {
        float acc[8][8];
        #pragma unroll
        for (int i = 0; i < 8; i++)
            #pragma unroll
            for (int j = 0; j < 8; j++) acc[i][j] = 0.f;
        for (int k = 0; k < 51; k++) {
            float a[8], b[8];
            #pragma unroll
            for (int i = 0; i < 8; i++) a[i] = bufA[(ty + 16 * i) * PA + k];
            #pragma unroll
            for (int j = 0; j < 8; j++) b[j] = bufB[(tx + 16 * j) * PA + k];
            #pragma unroll
            for (int i = 0; i < 8; i++)
                #pragma unroll
                for (int j = 0; j < 8; j++) acc[i][j] = fmaf(a[i], b[j], acc[i][j]);
        }
        __syncthreads();
        #pragma unroll
        for (int i = 0; i < 8; i++)
            #pragma unroll
            for (int j = 0; j < 8; j++) {
                int r = ty + 16 * i, c = tx + 16 * j;
                bufB[r * PA + c] = fmaxf(acc[i][j] + sb1[c], 0.f);
            }
        __syncthreads();
    }
    for (int e = tid; e < 128 * 128; e += 256) {
        int o = e >> 7, k = e & 127;
        bufA[o * PA + k] = w2[e];
    }
    __syncthreads();

    // GEMM2: h2 = relu(h1 @ W2^T + b2) -> bufA
    {
        float acc[8][8];
        #pragma unroll
        for (int i = 0; i < 8; i++)
            #pragma unroll
            for (int j = 0; j < 8; j++) acc[i][j] = 0.f;
        for (int k = 0; k < 128; k++) {
            float a[8], b[8];
            #pragma unroll
            for (int i = 0; i < 8; i++) a[i] = bufB[(ty + 16 * i) * PA + k];
            #pragma unroll
            for (int j = 0; j < 8; j++) b[j] = bufA[(tx + 16 * j) * PA + k];
            #pragma unroll
            for (int i = 0; i < 8; i++)
                #pragma unroll
                for (int j = 0; j < 8; j++) acc[i][j] = fmaf(a[i], b[j], acc[i][j]);
        }
        __syncthreads();
        #pragma unroll
        for (int i = 0; i < 8; i++)
            #pragma unroll
            for (int j = 0; j < 8; j++) {
                int r = ty + 16 * i, c = tx + 16 * j;
                bufA[r * PA + c] = fmaxf(acc[i][j] + sb2[c], 0.f);
            }
        __syncthreads();
    }
    for (int e = tid; e < 64 * 128; e += 256) {
        int o = e >> 7, k = e & 127;
        bufB[o * PA + k] = (o < 50) ? w3[o * 128 + k] : 0.f;
    }
    __syncthreads();

    // GEMM3: h3 = h2 @ W3^T + b3 -> g_x
    {
        float acc[8][4];
        #pragma unroll
        for (int i = 0; i < 8; i++)
            #pragma unroll
            for (int j = 0; j < 4; j++) acc[i][j] = 0.f;
        for (int k = 0; k < 128; k++) {
            float a[8], b[4];
            #pragma unroll
            for (int i = 0; i < 8; i++) a[i] = bufA[(ty + 16 * i) * PA + k];
            #pragma unroll
            for (int j = 0; j < 4; j++) b[j] = bufB[(tx + 16 * j) * PA + k];
            #pragma unroll
            for (int i = 0; i < 8; i++)
                #pragma unroll
                for (int j = 0; j < 4; j++) acc[i][j] = fmaf(a[i], b[j], acc[i][j]);
        }
        #pragma unroll
        for (int i = 0; i < 8; i++)
            #pragma unroll
            for (int j = 0; j < 4; j++) {
                int c = tx + 16 * j;
                if (c < 50) {
                    int r = ty + 16 * i;
                    g_x[(size_t)(base + r) * CC + c] = acc[i][j] + sb3[c];
                }
            }
        for (int e = tid; e < 128; e += 256)
            g_x[(size_t)(base + e) * CC + 50] = sLast[e];
    }
}

// =====================================================================
// Kernel 2: per-graph pipeline. 111.5 KB smem -> 2 CTAs/SM.
// =====================================================================
#define PX 53
#define PZ 65

__device__ __forceinline__ void gemm64_NT(const float* __restrict__ Aact, int pa,
                                          const float* __restrict__ Wt, int pw,
                                          int K, float* __restrict__ C, bool do_relu,
                                          int tx, int ty)
{
    float acc[4][4];
    #pragma unroll
    for (int i = 0; i < 4; i++)
        #pragma unroll
        for (int j = 0; j < 4; j++) acc[i][j] = 0.f;
    for (int k = 0; k < K; k++) {
        float a[4], b[4];
        #pragma unroll
        for (int i = 0; i < 4; i++) a[i] = Aact[(ty + 16 * i) * pa + k];
        #pragma unroll
        for (int j = 0; j < 4; j++) b[j] = Wt[(tx + 16 * j) * pw + k];
        #pragma unroll
        for (int i = 0; i < 4; i++)
            #pragma unroll
            for (int j = 0; j < 4; j++) acc[i][j] = fmaf(a[i], b[j], acc[i][j]);
    }
    __syncthreads();
    #pragma unroll
    for (int i = 0; i < 4; i++)
        #pragma unroll
        for (int j = 0; j < 4; j++) {
            float v = acc[i][j];
            if (do_relu) v = fmaxf(v, 0.f);
            C[(ty + 16 * i) * PZ + tx + 16 * j] = v;
        }
    __syncthreads();
}

__device__ __forceinline__ void gemm64_NN(const float* __restrict__ Ar, int pa,
                                          const float* __restrict__ Z, int K,
                                          float* __restrict__ C, bool do_relu,
                                          int tx, int ty)
{
    float acc[4][4];
    #pragma unroll
    for (int i = 0; i < 4; i++)
        #pragma unroll
        for (int j = 0; j < 4; j++) acc[i][j] = 0.f;
    for (int k = 0; k < K; k++) {
        float a[4], b[4];
        #pragma unroll
        for (int i = 0; i < 4; i++) a[i] = Ar[(ty + 16 * i) * pa + k];
        #pragma unroll
        for (int j = 0; j < 4; j++) b[j] = Z[k * PZ + tx + 16 * j];
        #pragma unroll
        for (int i = 0; i < 4; i++)
            #pragma unroll
            for (int j = 0; j < 4; j++) acc[i][j] = fmaf(a[i], b[j], acc[i][j]);
    }
    __syncthreads();
    #pragma unroll
    for (int i = 0; i < 4; i++)
        #pragma unroll
        for (int j = 0; j < 4; j++) {
            float v = acc[i][j];
            if (do_relu) v = fmaxf(v, 0.f);
            C[(ty + 16 * i) * PZ + tx + 16 * j] = v;
        }
    __syncthreads();
}

__global__ void __launch_bounds__(256, 2) k_main(
    const float* __restrict__ Wg1a, const float* __restrict__ Wg1b,
    const float* __restrict__ Wg2a, const float* __restrict__ Wg2b,
    float* __restrict__ dout)
{
    extern __shared__ float sh[];
    float* xs    = sh;                    // 80*PX
    float* WaBuf = xs + 80 * PX;          // 64*PX   (Wg1a, later Wg2a)
    float* An11s = WaBuf + 64 * PX;       // 64*PZ
    float* WbBuf = An11s + 64 * PZ;       // 64*PZ   (Wg1b padded, later theta)
    float* zb1   = WbBuf + 64 * PZ;       // 64*PZ
    float* zb2   = zb1 + 64 * PZ;         // 64*PZ
    float* z3    = zb2 + 64 * PZ;         // 16*PZ
    float* t2b   = z3 + 16 * PZ;          // 16*PZ
    float* Ls    = t2b + 16 * PZ;         // 16*PZ
    float* An22s = Ls + 16 * PZ;          // 16*17
    float* Wg2bs = An22s + 16 * 17;       // 64
    float* yhv   = Wg2bs + 64;            // 16
    float* z4v   = yhv + 16;              // 16
    float* sqv   = z4v + 16;              // 80
    unsigned int* AtmB = (unsigned int*)(sqv + 80); // 32

    const int tid = threadIdx.x;
    const int tx = tid & 15, ty = tid >> 4;
    const int b = blockIdx.x;
    const float* gx = g_x + (size_t)b * NN_ * CC;

    // -------- load phase --------
    for (int e = tid; e < 80 * 51; e += 256) xs[(e / 51) * PX + e % 51] = gx[e];
    for (int e = tid; e < 64 * 51; e += 256) WaBuf[(e / 51) * PX + e % 51] = Wg1a[e];
    for (int e = tid; e < 64 * 64; e += 256) {
        int o = e >> 6, k = e & 63;
        WbBuf[o * PZ + k] = (o < 50) ? Wg1b[o * 64 + k] : 0.f;
    }
    for (int e = tid; e < 64 * 64; e += 256) An11s[(e >> 6) * PZ + (e & 63)] = g_An11[e];
    if (tid < 256) An22s[(tid >> 4) * 17 + (tid & 15)] = g_An22[tid];
    if (tid < 32) AtmB[tid] = g_AtmBits[tid];
    if (tid >= 32 && tid < 96) Wg2bs[tid - 32] = Wg2b[tid - 32];
    __syncthreads();

    // -------- gcnn1 --------
    gemm64_NT(xs, PX, WaBuf, PX, 51, zb1, false, tx, ty);   // z1 = sg1 @ Wg1a^T
    // WaBuf free: reload with Wg2a for gcnn2
    for (int e = tid; e < 64 * 51; e += 256) WaBuf[(e / 51) * PX + e % 51] = Wg2a[e];
    gemm64_NN(An11s, PZ, zb1, 64, zb2, true, tx, ty);       // t1 = relu(An11 @ z1)
    gemm64_NT(zb2, PZ, WbBuf, PZ, 64, zb1, false, tx, ty);  // z2 = t1 @ Wg1b^T
    // WbBuf free: reload with theta (50 rows, cols >=50 zero)
    for (int e = tid; e < 50 * 64; e += 256) {
        int p = e >> 6, q = e & 63;
        WbBuf[p * PZ + q] = (q < 50) ? g_theta[p * 50 + q] : 0.f;
    }
    gemm64_NN(An11s, PZ, zb1, 64, zb2, false, tx, ty);      // x1 = An11 @ z2 -> zb2
    gemm64_NN(zb2, PZ, WbBuf, 50, zb1, false, tx, ty);      // u  = x1 @ theta -> zb1

    // -------- V = xf @ theta (16x64) -> z3 --------
    {
        float acc[4] = {0.f, 0.f, 0.f, 0.f};
        for (int k = 0; k < 50; k++) {
            float a = xs[(64 + ty) * PX + k];
            #pragma unroll
            for (int j = 0; j < 4; j++) acc[j] = fmaf(a, WbBuf[k * PZ + tx + 16 * j], acc[j]);
        }
        __syncthreads();
        #pragma unroll
        for (int j = 0; j < 4; j++) z3[ty * PZ + tx + 16 * j] = acc[j];
        __syncthreads();
    }

    // -------- q[j][i] = (xp_i - xf_j) . (u_i - v_j); masked logits -> Ls --------
    {
        float cf = g_coef;
        float acc[4] = {0.f, 0.f, 0.f, 0.f};
        for (int k = 0; k < 50; k++) {
            float xfk = xs[(64 + ty) * PX + k];
            float vk  = z3[ty * PZ + k];
            #pragma unroll
            for (int j = 0; j < 4; j++) {
                int i = tx + 16 * j;
                acc[j] = fmaf(zb2[i * PZ + k] - xfk, zb1[i * PZ + k] - vk, acc[j]);
            }
        }
        unsigned int m0 = AtmB[ty * 2], m1 = AtmB[ty * 2 + 1];
        __syncthreads();
        #pragma unroll
        for (int j = 0; j < 4; j++) {
            int i = tx + 16 * j;
            bool on = (i < 32) ? ((m0 >> i) & 1u) : ((m1 >> (i - 32)) & 1u);
            Ls[ty * PZ + i] = on ? (cf * acc[j]) : NEGV;
        }
        __syncthreads();
    }

    // -------- softmax over j (per past index i) --------
    if (tid < 64) {
        int i = tid;
        float m = NEGV;
        for (int j = 0; j < 16; j++) m = fmaxf(m, Ls[j * PZ + i]);
        float s = 0.f;
        for (int j = 0; j < 16; j++) {
            float e = expf(Ls[j * PZ + i] - m);
            Ls[j * PZ + i] = e;
            s += e;
        }
        float inv = 1.f / s;
        for (int j = 0; j < 16; j++) Ls[j * PZ + i] *= inv;
    }
    __syncthreads();

    // -------- yh[j] then splice into xs --------
    if (tid < 16) {
        float s = 0.f;
        for (int i = 0; i < 64; i++) s = fmaf(Ls[tid * PZ + i], xs[i * PX + 50], s);
        yhv[tid] = s;
    }
    __syncthreads();
    if (tid < 16) xs[(64 + tid) * PX + 50] = yhv[tid];
    __syncthreads();

    // -------- gcnn2 (WaBuf now holds Wg2a) --------
    {
        float acc[4] = {0.f, 0.f, 0.f, 0.f};
        for (int k = 0; k < 51; k++) {
            float a = xs[(64 + ty) * PX + k];
            #pragma unroll
            for (int j = 0; j < 4; j++) acc[j] = fmaf(a, WaBuf[(tx + 16 * j) * PX + k], acc[j]);
        }
        __syncthreads();
        #pragma unroll
        for (int j = 0; j < 4; j++) z3[ty * PZ + tx + 16 * j] = acc[j];
        __syncthreads();
    }
    {
        float acc[4] = {0.f, 0.f, 0.f, 0.f};
        for (int q = 0; q < 16; q++) {
            float a = An22s[ty * 17 + q];
            #pragma unroll
            for (int j = 0; j < 4; j++) acc[j] = fmaf(a, z3[q * PZ + tx + 16 * j], acc[j]);
        }
        __syncthreads();
        #pragma unroll
        for (int j = 0; j < 4; j++) t2b[ty * PZ + tx + 16 * j] = fmaxf(acc[j], 0.f);
        __syncthreads();
    }
    if (tid < 16) {
        float s = 0.f;
        for (int c = 0; c < 64; c++) s = fmaf(t2b[tid * PZ + c], Wg2bs[c], s);
        z4v[tid] = s;
    }
    __syncthreads();
    if (tid < 16) {
        float s = 0.f;
        for (int q = 0; q < 16; q++) s = fmaf(An22s[tid * 17 + q], z4v[q], s);
        dout[b * 16 + tid] = s;
    }

    // -------- pairwise dist on xc (80x51) --------
    if (tid < 80) {
        float s = 0.f;
        for (int c = 0; c < 51; c++) {
            float v = xs[tid * PX + c];
            s = fmaf(v, v, s);
        }
        sqv[tid] = s;
    }
    __syncthreads();
    {
        float acc[5][5];
        #pragma unroll
        for (int i = 0; i < 5; i++)
            #pragma unroll
            for (int j = 0; j < 5; j++) acc[i][j] = 0.f;
        for (int k = 0; k < 51; k++) {
            float a[5], bb[5];
            #pragma unroll
            for (int i = 0; i < 5; i++) a[i] = xs[(ty * 5 + i) * PX + k];
            #pragma unroll
            for (int j = 0; j < 5; j++) bb[j] = xs[(tx * 5 + j) * PX + k];
            #pragma unroll
            for (int i = 0; i < 5; i++)
                #pragma unroll
                for (int j = 0; j < 5; j++) acc[i][j] = fmaf(a[i], bb[j], acc[i][j]);
        }
        float* dd = dout + DIST_OFF + (size_t)b * 6400;
        #pragma unroll
        for (int i = 0; i < 5; i++)
            #pragma unroll
            for (int j = 0; j < 5; j++) {
                int n = ty * 5 + i, m = tx * 5 + j;
                float d2 = sqv[n] + sqv[m] - 2.f * acc[i][j];
                dd[n * 80 + m] = (d2 > 0.f) ? sqrtf(d2) : 0.f;
            }
    }
}

// =====================================================================
// launcher
// =====================================================================
extern "C" void kernel_launch(void* const* d_in, const int* in_sizes, int n_in,
                              void* d_out, int out_size)
{
    const float* data  = (const float*)d_in[0];
    const float* emb0  = (const float*)d_in[1];
    const float* emb1  = (const float*)d_in[2];
    const float* emb2  = (const float*)d_in[3];
    const float* w1    = (const float*)d_in[4];
    const float* b1    = (const float*)d_in[5];
    const float* w2    = (const float*)d_in[6];
    const float* b2    = (const float*)d_in[7];
    const float* w3    = (const float*)d_in[8];
    const float* b3    = (const float*)d_in[9];
    const float* M     = (const float*)d_in[10];
    const float* Wg1a  = (const float*)d_in[11];
    const float* Wg1b  = (const float*)d_in[12];
    const float* Wk    = (const float*)d_in[13];
    const float* smoothing = (const float*)d_in[14];
    const float* Wg2a  = (const float*)d_in[15];
    const float* Wg2b  = (const float*)d_in[16];
    float* out = (float*)d_out;

    const int SMEM_MLP  = (2 * 128 * PA + 128 + 128 + 64 + 128) * 4;
    const int SMEM_MAIN = (80 * PX + 64 * PX + 4 * 64 * PZ + 3 * 16 * PZ +
                           16 * 17 + 64 + 16 + 16 + 80 + 32) * 4;

    cudaFuncSetAttribute(k_mlp, cudaFuncAttributeMaxDynamicSharedMemorySize, SMEM_MLP);
    cudaFuncSetAttribute(k_main, cudaFuncAttributeMaxDynamicSharedMemorySize, SMEM_MAIN);

    k_setup<<<1, 1024>>>(M, Wk, smoothing, out + A_OFF);
    k_mlp<<<640, 256, SMEM_MLP>>>(data, emb0, emb1, emb2, w1, b1, w2, b2, w3, b3);
    k_main<<<1024, 256, SMEM_MAIN>>>(Wg1a, Wg1b, Wg2a, Wg2b, out);
}

// round 4
// speedup vs baseline: 1.4844x; 1.2626x over previous
#include <cuda_runtime.h>
#include <math.h>

// ---------------- problem constants ----------------
#define BB    1024
#define NN_   80
#define PAST_ 64
#define FUT_  16
#define CC    51     // OUTP
#define DM_   26
#define NEGV  -1e30f

#define DIST_OFF 16384
#define A_OFF    (16384 + 1024*6400)

typedef unsigned long long u64;

// ---------------- f32x2 packed helpers ----------------
__device__ __forceinline__ u64 pk2(float lo, float hi) {
    u64 r; asm("mov.b64 %0,{%1,%2};" : "=l"(r) : "f"(lo), "f"(hi)); return r;
}
__device__ __forceinline__ u64 dup2(float v) { return pk2(v, v); }
__device__ __forceinline__ void up2(u64 v, float& a, float& b) {
    asm("mov.b64 {%0,%1},%2;" : "=f"(a), "=f"(b) : "l"(v));
}
__device__ __forceinline__ u64 fma2(u64 a, u64 b, u64 c) {
    u64 d; asm("fma.rn.f32x2 %0,%1,%2,%3;" : "=l"(d) : "l"(a), "l"(b), "l"(c)); return d;
}

// ---------------- device scratch ----------------
__device__ float g_x[BB * NN_ * CC];
__device__ float g_An11[64 * 64];
__device__ float g_An22[16 * 16];
__device__ unsigned int g_AtmBits[32];
__device__ float g_theta[50 * 50];
__device__ float g_coef;

// =====================================================================
// setup work, executed by one extra block of k_mlp (256 threads)
// =====================================================================
__device__ void do_setup(float* sh, const float* __restrict__ M,
                         const float* __restrict__ Wk,
                         const float* __restrict__ smoothing,
                         float* __restrict__ outA)
{
    float* sM = sh;                 // 80*26
    float* sA = sM + NN_ * DM_;     // 80*80
    float* d1 = sA + NN_ * NN_;     // 64
    float* d2 = d1 + 64;            // 16
    const int tid = threadIdx.x;
    const int lane = tid & 31, warp = tid >> 5;   // 8 warps

    for (int e = tid; e < NN_ * DM_; e += 256) sM[e] = M[e];
    for (int e = tid; e < NN_ * NN_; e += 256) sA[e] = 0.f;
    __syncthreads();

    for (int p = warp; p < NN_; p += 8) {
        float vals[3];
        float mx = NEGV;
        int cnt = 0;
        for (int q = lane; q < p; q += 32) {
            float s = 0.f;
            #pragma unroll
            for (int k = 0; k < DM_; k++) s = fmaf(sM[p * DM_ + k], sM[q * DM_ + k], s);
            s = fmaxf(s, 0.f);
            vals[cnt++] = s;
            mx = fmaxf(mx, s);
        }
        #pragma unroll
        for (int off = 16; off; off >>= 1) mx = fmaxf(mx, __shfl_xor_sync(0xffffffffu, mx, off));
        float sum = 0.f;
        for (int c = 0; c < cnt; c++) { vals[c] = expf(vals[c] - mx); sum += vals[c]; }
        #pragma unroll
        for (int off = 16; off; off >>= 1) sum += __shfl_xor_sync(0xffffffffu, sum, off);
        float inv = (p > 0) ? 1.f / sum : 0.f;
        cnt = 0;
        for (int q = lane; q < p; q += 32) sA[p * NN_ + q] = vals[cnt++] * inv;
    }
    __syncthreads();

    for (int e = tid; e < NN_ * NN_; e += 256) outA[e] = sA[e];

    if (tid < 64) {
        int c = 0;
        for (int q = 0; q < 64; q++) c += (sA[tid * NN_ + q] > 1e-15f) ? 1 : 0;
        d1[tid] = rsqrtf(1.f + (float)c);
    } else if (tid < 80) {
        int p = tid;
        int c = 0;
        for (int q = 64; q < 80; q++) c += (sA[p * NN_ + q] > 1e-15f) ? 1 : 0;
        d2[tid - 64] = rsqrtf(1.f + (float)c);
    }
    __syncthreads();

    for (int e = tid; e < 64 * 64; e += 256) {
        int p = e >> 6, q = e & 63;
        g_An11[e] = d1[p] * sA[p * NN_ + q] * d1[q];
    }
    if (tid < 256) {
        int p = tid >> 4, q = tid & 15;
        g_An22[tid] = d2[p] * sA[(64 + p) * NN_ + 64 + q] * d2[q];
    }

    if (tid < 16) {
        int p = 64 + tid;
        float mx = NEGV;
        for (int i = 0; i < 64; i++) {
            float a = sA[p * NN_ + i];
            mx = fmaxf(mx, (a != 0.f) ? a : NEGV);
        }
        float sum = 0.f;
        for (int i = 0; i < 64; i++) {
            float a = sA[p * NN_ + i];
            sum += expf(((a != 0.f) ? a : NEGV) - mx);
        }
        float inv = 1.f / sum;
        unsigned int b0 = 0u, b1 = 0u;
        for (int i = 0; i < 64; i++) {
            float a = sA[p * NN_ + i];
            float v = expf(((a != 0.f) ? a : NEGV) - mx) * inv;
            if (v >= 0.004f) {
                if (i < 32) b0 |= (1u << i);
                else        b1 |= (1u << (i - 32));
            }
        }
        g_AtmBits[tid * 2]     = b0;
        g_AtmBits[tid * 2 + 1] = b1;
    }

    for (int e = tid; e < 50 * 50; e += 256) {
        int p = e / 50, q = e % 50;
        float s = 0.f;
        #pragma unroll 8
        for (int k = 0; k < 64; k++) s = fmaf(Wk[p * 64 + k], Wk[q * 64 + k], s);
        g_theta[e] = s;
    }

    if (tid == 0) {
        float sg = 1.f / (1.f + expf(-smoothing[0]));
        g_coef = -0.5f / (sg * 0.01f);
    }
}

// =====================================================================
// Kernel 1: gather + 3-layer MLP with packed f32x2 FMA; block 640 = setup
// =====================================================================
#define PT  129   // token buffers pitch
#define PWB 130   // k-major weight buffer pitch (even -> LDS.64 pairs)

__global__ void __launch_bounds__(256) k_mlp(
    const float* __restrict__ data,
    const float* __restrict__ emb0, const float* __restrict__ emb1, const float* __restrict__ emb2,
    const float* __restrict__ w1, const float* __restrict__ b1,
    const float* __restrict__ w2, const float* __restrict__ b2,
    const float* __restrict__ w3, const float* __restrict__ b3,
    const float* __restrict__ M, const float* __restrict__ Wk,
    const float* __restrict__ smoothing, float* __restrict__ outA)
{
    extern __shared__ float sh[];

    if (blockIdx.x == 640) { do_setup(sh, M, Wk, smoothing, outA); return; }

    float* T0  = sh;                     // 128*PT
    float* T1  = T0 + 128 * PT;          // 128*PT
    float* sW  = T1 + 128 * PT;          // 128*PWB  (k-major weights)
    float* sb1 = sW + 128 * PWB;         // 128
    float* sb2 = sb1 + 128;              // 128
    float* sb3 = sb2 + 128;              // 64
    float* sLast = sb3 + 64;             // 128

    const int tid = threadIdx.x;
    const int tx = tid & 15, ty = tid >> 4;
    const int base = blockIdx.x * 128;

    for (int e = tid; e < 128; e += 256) { sb1[e] = b1[e]; sb2[e] = b2[e]; }
    for (int e = tid; e < 64; e += 256) sb3[e] = (e < 50) ? b3[e] : 0.f;
    for (int e = tid; e < 128; e += 256) sLast[e] = data[(size_t)(base + e) * 6 + 5];

    // gather X (128 x 51) token-major into T0
    for (int e = tid; e < 128 * 51; e += 256) {
        int t = e / 51, c = e % 51;
        const float* dr = data + (size_t)(base + t) * 6;
        float v;
        if (c < 32)      { int i0 = (int)dr[0]; v = emb0[i0 * 32 + c]; }
        else if (c < 40) { int i1 = (int)dr[1]; v = emb1[i1 * 8 + (c - 32)]; }
        else if (c < 48) { int i2 = (int)dr[2]; v = emb2[i2 * 8 + (c - 40)]; }
        else             { v = dr[3 + (c - 48)]; }
        T0[t * PT + c] = v;
    }
    // W1 (128 x 51) -> k-major sW[k*PWB + o]
    for (int e = tid; e < 128 * 51; e += 256) {
        int o = e / 51, k = e % 51;
        sW[k * PWB + o] = w1[e];
    }
    __syncthreads();

    // ---- GEMM1: h1 = relu(X @ W1^T + b1) -> T1 ----
    {
        u64 acc[8][4];
        #pragma unroll
        for (int i = 0; i < 8; i++)
            #pragma unroll
            for (int j = 0; j < 4; j++) acc[i][j] = 0ull;
        for (int k = 0; k < 51; k++) {
            u64 ad[8], b2v[4];
            #pragma unroll
            for (int i = 0; i < 8; i++) ad[i] = dup2(T0[(ty + 16 * i) * PT + k]);
            #pragma unroll
            for (int j = 0; j < 4; j++)
                b2v[j] = *reinterpret_cast<const u64*>(&sW[k * PWB + 2 * tx + 32 * j]);
            #pragma unroll
            for (int i = 0; i < 8; i++)
                #pragma unroll
                for (int j = 0; j < 4; j++) acc[i][j] = fma2(ad[i], b2v[j], acc[i][j]);
        }
        __syncthreads();
        #pragma unroll
        for (int i = 0; i < 8; i++)
            #pragma unroll
            for (int j = 0; j < 4; j++) {
                int r = ty + 16 * i, c = 2 * tx + 32 * j;
                float v0, v1; up2(acc[i][j], v0, v1);
                T1[r * PT + c]     = fmaxf(v0 + sb1[c], 0.f);
                T1[r * PT + c + 1] = fmaxf(v1 + sb1[c + 1], 0.f);
            }
    }
    // W2 (128 x 128) -> k-major
    for (int e = tid; e < 128 * 128; e += 256) {
        int o = e >> 7, k = e & 127;
        sW[k * PWB + o] = w2[e];
    }
    __syncthreads();

    // ---- GEMM2: h2 = relu(h1 @ W2^T + b2) -> T0 ----
    {
        u64 acc[8][4];
        #pragma unroll
        for (int i = 0; i < 8; i++)
            #pragma unroll
            for (int j = 0; j < 4; j++) acc[i][j] = 0ull;
        for (int k = 0; k < 128; k++) {
            u64 ad[8], b2v[4];
            #pragma unroll
            for (int i = 0; i < 8; i++) ad[i] = dup2(T1[(ty + 16 * i) * PT + k]);
            #pragma unroll
            for (int j = 0; j < 4; j++)
                b2v[j] = *reinterpret_cast<const u64*>(&sW[k * PWB + 2 * tx + 32 * j]);
            #pragma unroll
            for (int i = 0; i < 8; i++)
                #pragma unroll
                for (int j = 0; j < 4; j++) acc[i][j] = fma2(ad[i], b2v[j], acc[i][j]);
        }
        __syncthreads();
        #pragma unroll
        for (int i = 0; i < 8; i++)
            #pragma unroll
            for (int j = 0; j < 4; j++) {
                int r = ty + 16 * i, c = 2 * tx + 32 * j;
                float v0, v1; up2(acc[i][j], v0, v1);
                T0[r * PT + c]     = fmaxf(v0 + sb2[c], 0.f);
                T0[r * PT + c + 1] = fmaxf(v1 + sb2[c + 1], 0.f);
            }
    }
    // W3 (50 x 128, pad to 64) -> k-major
    for (int e = tid; e < 64 * 128; e += 256) {
        int o = e >> 7, k = e & 127;
        sW[k * PWB + o] = (o < 50) ? w3[o * 128 + k] : 0.f;
    }
    __syncthreads();

    // ---- GEMM3: h3 = h2 @ W3^T + b3 -> g_x ----
    {
        u64 acc[8][2];
        #pragma unroll
        for (int i = 0; i < 8; i++) { acc[i][0] = 0ull; acc[i][1] = 0ull; }
        for (int k = 0; k < 128; k++) {
            u64 ad[8], b2v[2];
            #pragma unroll
            for (int i = 0; i < 8; i++) ad[i] = dup2(T0[(ty + 16 * i) * PT + k]);
            #pragma unroll
            for (int j = 0; j < 2; j++)
                b2v[j] = *reinterpret_cast<const u64*>(&sW[k * PWB + 2 * tx + 32 * j]);
            #pragma unroll
            for (int i = 0; i < 8; i++)
                #pragma unroll
                for (int j = 0; j < 2; j++) acc[i][j] = fma2(ad[i], b2v[j], acc[i][j]);
        }
        #pragma unroll
        for (int i = 0; i < 8; i++)
            #pragma unroll
            for (int j = 0; j < 2; j++) {
                int r = ty + 16 * i, c = 2 * tx + 32 * j;
                float v0, v1; up2(acc[i][j], v0, v1);
                if (c < 50)     g_x[(size_t)(base + r) * CC + c]     = v0 + sb3[c];
                if (c + 1 < 50) g_x[(size_t)(base + r) * CC + c + 1] = v1 + sb3[c + 1];
            }
        for (int e = tid; e < 128; e += 256)
            g_x[(size_t)(base + e) * CC + 50] = sLast[e];
    }
}

// =====================================================================
// Kernel 2: per-graph pipeline with f32x2 gemms. 112.6 KB -> 2 CTAs/SM.
// =====================================================================
#define PX 53
#define PZ 66
#define PAN 65

// C(64x64) = A(64xK, row-major pitch pa) @ B(Kx64, k-major pitch PZ)
__device__ __forceinline__ void gemm64_2(const float* __restrict__ A, int pa,
                                         const float* __restrict__ B, int K,
                                         float* __restrict__ C, bool do_relu,
                                         int tx, int ty)
{
    u64 acc[4][2];
    #pragma unroll
    for (int i = 0; i < 4; i++) { acc[i][0] = 0ull; acc[i][1] = 0ull; }
    for (int k = 0; k < K; k++) {
        u64 ad[4], b2v[2];
        #pragma unroll
        for (int i = 0; i < 4; i++) ad[i] = dup2(A[(ty + 16 * i) * pa + k]);
        #pragma unroll
        for (int j = 0; j < 2; j++)
            b2v[j] = *reinterpret_cast<const u64*>(&B[k * PZ + 2 * tx + 32 * j]);
        #pragma unroll
        for (int i = 0; i < 4; i++)
            #pragma unroll
            for (int j = 0; j < 2; j++) acc[i][j] = fma2(ad[i], b2v[j], acc[i][j]);
    }
    __syncthreads();
    #pragma unroll
    for (int i = 0; i < 4; i++)
        #pragma unroll
        for (int j = 0; j < 2; j++) {
            int r = ty + 16 * i, c = 2 * tx + 32 * j;
            float v0, v1; up2(acc[i][j], v0, v1);
            if (do_relu) { v0 = fmaxf(v0, 0.f); v1 = fmaxf(v1, 0.f); }
            C[r * PZ + c] = v0;
            C[r * PZ + c + 1] = v1;
        }
    __syncthreads();
}

__global__ void __launch_bounds__(256, 2) k_main(
    const float* __restrict__ Wg1a, const float* __restrict__ Wg1b,
    const float* __restrict__ Wg2a, const float* __restrict__ Wg2b,
    float* __restrict__ dout)
{
    extern __shared__ float sh[];
    float* xs    = sh;                    // 80*PX
    float* WaT   = xs + 80 * PX;          // 52*PZ  (Wg1a^T then Wg2a^T, k-major)
    float* An11s = WaT + 52 * PZ;         // 64*PAN
    float* WbT   = An11s + 64 * PAN;      // 64*PZ  (Wg1b^T then theta, k-major)
    float* zb1   = WbT + 64 * PZ;         // 64*PZ
    float* zb2   = zb1 + 64 * PZ;         // 64*PZ
    float* z3    = zb2 + 64 * PZ;         // 16*PZ
    float* t2b   = z3 + 16 * PZ;          // 16*PZ
    float* Ls    = t2b + 16 * PZ;         // 16*PZ
    float* An22s = Ls + 16 * PZ;          // 16*17
    float* Wg2bs = An22s + 16 * 17;       // 64
    float* yhv   = Wg2bs + 64;            // 16
    float* z4v   = yhv + 16;              // 16
    float* sqv   = z4v + 16;              // 80
    unsigned int* AtmB = (unsigned int*)(sqv + 80); // 32

    const int tid = threadIdx.x;
    const int tx = tid & 15, ty = tid >> 4;
    const int b = blockIdx.x;
    const float* gx = g_x + (size_t)b * NN_ * CC;

    // -------- load phase --------
    for (int e = tid; e < 80 * 51; e += 256) xs[(e / 51) * PX + e % 51] = gx[e];
    for (int e = tid; e < 64 * 51; e += 256) {
        int o = e / 51, k = e % 51;
        WaT[k * PZ + o] = Wg1a[e];
    }
    for (int e = tid; e < 64 * 64; e += 256) {
        int o = e >> 6, k = e & 63;
        WbT[k * PZ + o] = (o < 50) ? Wg1b[o * 64 + k] : 0.f;
    }
    for (int e = tid; e < 64 * 64; e += 256) An11s[(e >> 6) * PAN + (e & 63)] = g_An11[e];
    if (tid < 256) An22s[(tid >> 4) * 17 + (tid & 15)] = g_An22[tid];
    if (tid < 32) AtmB[tid] = g_AtmBits[tid];
    if (tid >= 32 && tid < 96) Wg2bs[tid - 32] = Wg2b[tid - 32];
    __syncthreads();

    // -------- gcnn1 --------
    gemm64_2(xs, PX, WaT, 51, zb1, false, tx, ty);      // z1 = sg1 @ Wg1a^T
    // WaT free: reload with Wg2a^T
    for (int e = tid; e < 64 * 51; e += 256) {
        int o = e / 51, k = e % 51;
        WaT[k * PZ + o] = Wg2a[e];
    }
    gemm64_2(An11s, PAN, zb1, 64, zb2, true, tx, ty);   // t1 = relu(An11 @ z1)
    gemm64_2(zb2, PZ, WbT, 64, zb1, false, tx, ty);     // z2 = t1 @ Wg1b^T
    // WbT free: reload with theta (k-major, 50 rows)
    for (int e = tid; e < 50 * 64; e += 256) {
        int k = e >> 6, q = e & 63;
        WbT[k * PZ + q] = (q < 50) ? g_theta[k * 50 + q] : 0.f;
    }
    gemm64_2(An11s, PAN, zb1, 64, zb2, false, tx, ty);  // x1 = An11 @ z2 -> zb2
    gemm64_2(zb2, PZ, WbT, 50, zb1, false, tx, ty);     // u  = x1 @ theta -> zb1

    // -------- V = xf @ theta (16x64) -> z3 --------
    {
        u64 acc[2] = {0ull, 0ull};
        for (int k = 0; k < 50; k++) {
            u64 ad = dup2(xs[(64 + ty) * PX + k]);
            #pragma unroll
            for (int j = 0; j < 2; j++)
                acc[j] = fma2(ad, *reinterpret_cast<const u64*>(&WbT[k * PZ + 2 * tx + 32 * j]), acc[j]);
        }
        __syncthreads();
        #pragma unroll
        for (int j = 0; j < 2; j++) {
            float v0, v1; up2(acc[j], v0, v1);
            int c = 2 * tx + 32 * j;
            z3[ty * PZ + c] = v0;
            z3[ty * PZ + c + 1] = v1;
        }
        __syncthreads();
    }

    // -------- q[j][i] = (xp_i - xf_j) . (u_i - v_j); masked logits -> Ls --------
    {
        float cf = g_coef;
        float acc[4] = {0.f, 0.f, 0.f, 0.f};
        for (int k = 0; k < 50; k++) {
            float xfk = xs[(64 + ty) * PX + k];
            float vk  = z3[ty * PZ + k];
            #pragma unroll
            for (int j = 0; j < 4; j++) {
                int i = tx + 16 * j;
                acc[j] = fmaf(zb2[i * PZ + k] - xfk, zb1[i * PZ + k] - vk, acc[j]);
            }
        }
        unsigned int m0 = AtmB[ty * 2], m1 = AtmB[ty * 2 + 1];
        __syncthreads();
        #pragma unroll
        for (int j = 0; j < 4; j++) {
            int i = tx + 16 * j;
            bool on = (i < 32) ? ((m0 >> i) & 1u) : ((m1 >> (i - 32)) & 1u);
            Ls[ty * PZ + i] = on ? (cf * acc[j]) : NEGV;
        }
        __syncthreads();
    }

    // -------- softmax over j --------
    if (tid < 64) {
        int i = tid;
        float m = NEGV;
        for (int j = 0; j < 16; j++) m = fmaxf(m, Ls[j * PZ + i]);
        float s = 0.f;
        for (int j = 0; j < 16; j++) {
            float e = expf(Ls[j * PZ + i] - m);
            Ls[j * PZ + i] = e;
            s += e;
        }
        float inv = 1.f / s;
        for (int j = 0; j < 16; j++) Ls[j * PZ + i] *= inv;
    }
    __syncthreads();

    // -------- yh, splice --------
    if (tid < 16) {
        float s = 0.f;
        for (int i = 0; i < 64; i++) s = fmaf(Ls[tid * PZ + i], xs[i * PX + 50], s);
        yhv[tid] = s;
    }
    __syncthreads();
    if (tid < 16) xs[(64 + tid) * PX + 50] = yhv[tid];
    __syncthreads();

    // -------- gcnn2 --------
    {   // z3g = x2 @ Wg2a^T (WaT holds Wg2a^T now)
        u64 acc[2] = {0ull, 0ull};
        for (int k = 0; k < 51; k++) {
            u64 ad = dup2(xs[(64 + ty) * PX + k]);
            #pragma unroll
            for (int j = 0; j < 2; j++)
                acc[j] = fma2(ad, *reinterpret_cast<const u64*>(&WaT[k * PZ + 2 * tx + 32 * j]), acc[j]);
        }
        __syncthreads();
        #pragma unroll
        for (int j = 0; j < 2; j++) {
            float v0, v1; up2(acc[j], v0, v1);
            int c = 2 * tx + 32 * j;
            z3[ty * PZ + c] = v0;
            z3[ty * PZ + c + 1] = v1;
        }
        __syncthreads();
    }
    {   // t2 = relu(An22 @ z3g)
        u64 acc[2] = {0ull, 0ull};
        for (int q = 0; q < 16; q++) {
            u64 ad = dup2(An22s[ty * 17 + q]);
            #pragma unroll
            for (int j = 0; j < 2; j++)
                acc[j] = fma2(ad, *reinterpret_cast<const u64*>(&z3[q * PZ + 2 * tx + 32 * j]), acc[j]);
        }
        __syncthreads();
        #pragma unroll
        for (int j = 0; j < 2; j++) {
            float v0, v1; up2(acc[j], v0, v1);
            int c = 2 * tx + 32 * j;
            t2b[ty * PZ + c]     = fmaxf(v0, 0.f);
            t2b[ty * PZ + c + 1] = fmaxf(v1, 0.f);
        }
        __syncthreads();
    }
    if (tid < 16) {
        float s = 0.f;
        for (int c = 0; c < 64; c++) s = fmaf(t2b[tid * PZ + c], Wg2bs[c], s);
        z4v[tid] = s;
    }
    __syncthreads();
    if (tid < 16) {
        float s = 0.f;
        for (int q = 0; q < 16; q++) s = fmaf(An22s[tid * 17 + q], z4v[q], s);
        dout[b * 16 + tid] = s;
    }

    // -------- pairwise dist on xc (80x51) --------
    if (tid < 80) {
        float s = 0.f;
        for (int c = 0; c < 51; c++) {
            float v = xs[tid * PX + c];
            s = fmaf(v, v, s);
        }
        sqv[tid] = s;
    }
    __syncthreads();
    {
        float acc[5][5];
        #pragma unroll
        for (int i = 0; i < 5; i++)
            #pragma unroll
            for (int j = 0; j < 5; j++) acc[i][j] = 0.f;
        for (int k = 0; k < 51; k++) {
            float a[5], bb[5];
            #pragma unroll
            for (int i = 0; i < 5; i++) a[i] = xs[(ty * 5 + i) * PX + k];
            #pragma unroll
            for (int j = 0; j < 5; j++) bb[j] = xs[(tx * 5 + j) * PX + k];
            #pragma unroll
            for (int i = 0; i < 5; i++)
                #pragma unroll
                for (int j = 0; j < 5; j++) acc[i][j] = fmaf(a[i], bb[j], acc[i][j]);
        }
        float* dd = dout + DIST_OFF + (size_t)b * 6400;
        #pragma unroll
        for (int i = 0; i < 5; i++)
            #pragma unroll
            for (int j = 0; j < 5; j++) {
                int n = ty * 5 + i, m = tx * 5 + j;
                float d2 = sqv[n] + sqv[m] - 2.f * acc[i][j];
                dd[n * 80 + m] = (d2 > 0.f) ? sqrtf(d2) : 0.f;
            }
    }
}

// =====================================================================
// launcher
// =====================================================================
extern "C" void kernel_launch(void* const* d_in, const int* in_sizes, int n_in,
                              void* d_out, int out_size)
{
    const float* data  = (const float*)d_in[0];
    const float* emb0  = (const float*)d_in[1];
    const float* emb1  = (const float*)d_in[2];
    const float* emb2  = (const float*)d_in[3];
    const float* w1    = (const float*)d_in[4];
    const float* b1    = (const float*)d_in[5];
    const float* w2    = (const float*)d_in[6];
    const float* b2    = (const float*)d_in[7];
    const float* w3    = (const float*)d_in[8];
    const float* b3    = (const float*)d_in[9];
    const float* M     = (const float*)d_in[10];
    const float* Wg1a  = (const float*)d_in[11];
    const float* Wg1b  = (const float*)d_in[12];
    const float* Wk    = (const float*)d_in[13];
    const float* smoothing = (const float*)d_in[14];
    const float* Wg2a  = (const float*)d_in[15];
    const float* Wg2b  = (const float*)d_in[16];
    float* out = (float*)d_out;

    const int SMEM_MLP  = (2 * 128 * PT + 128 * PWB + 128 + 128 + 64 + 128) * 4;
    const int SMEM_MAIN = (80 * PX + 52 * PZ + 64 * PAN + 3 * 64 * PZ + 3 * 16 * PZ +
                           16 * 17 + 64 + 16 + 16 + 80 + 32) * 4;

    cudaFuncSetAttribute(k_mlp, cudaFuncAttributeMaxDynamicSharedMemorySize, SMEM_MLP);
    cudaFuncSetAttribute(k_main, cudaFuncAttributeMaxDynamicSharedMemorySize, SMEM_MAIN);

    k_mlp<<<641, 256, SMEM_MLP>>>(data, emb0, emb1, emb2, w1, b1, w2, b2, w3, b3,
                                  M, Wk, smoothing, out + A_OFF);
    k_main<<<1024, 256, SMEM_MAIN>>>(Wg1a, Wg1b, Wg2a, Wg2b, out);
}

// round 5
// speedup vs baseline: 1.5016x; 1.0115x over previous
#include <cuda_runtime.h>
#include <math.h>

// ---------------- problem constants ----------------
#define BB    1024
#define NN_   80
#define CC    51     // OUTP
#define DM_   26
#define NEGV  -1e30f

#define DIST_OFF 16384
#define A_OFF    (16384 + 1024*6400)

typedef unsigned long long u64;

// ---------------- f32x2 packed helpers ----------------
__device__ __forceinline__ u64 pk2(float lo, float hi) {
    u64 r; asm("mov.b64 %0,{%1,%2};" : "=l"(r) : "f"(lo), "f"(hi)); return r;
}
__device__ __forceinline__ u64 dup2(float v) { return pk2(v, v); }
__device__ __forceinline__ void up2(u64 v, float& a, float& b) {
    asm("mov.b64 {%0,%1},%2;" : "=f"(a), "=f"(b) : "l"(v));
}
__device__ __forceinline__ u64 fma2(u64 a, u64 b, u64 c) {
    u64 d; asm("fma.rn.f32x2 %0,%1,%2,%3;" : "=l"(d) : "l"(a), "l"(b), "l"(c)); return d;
}

// ---------------- device scratch ----------------
__device__ float g_x[BB * NN_ * CC];
__device__ float g_An11[64 * 64];
__device__ float g_An22[16 * 16];
__device__ unsigned int g_AtmBits[32];
__device__ float g_theta[50 * 50];
__device__ float g_coef;

// =====================================================================
// setup work, executed by one extra block of k_mlp (256 threads)
// =====================================================================
__device__ void do_setup(float* sh, const float* __restrict__ M,
                         const float* __restrict__ Wk,
                         const float* __restrict__ smoothing,
                         float* __restrict__ outA)
{
    float* sM = sh;                 // 80*26
    float* sA = sM + NN_ * DM_;     // 80*80
    float* d1 = sA + NN_ * NN_;     // 64
    float* d2 = d1 + 64;            // 16
    const int tid = threadIdx.x;
    const int lane = tid & 31, warp = tid >> 5;

    for (int e = tid; e < NN_ * DM_; e += 256) sM[e] = M[e];
    for (int e = tid; e < NN_ * NN_; e += 256) sA[e] = 0.f;
    __syncthreads();

    for (int p = warp; p < NN_; p += 8) {
        float vals[3];
        float mx = NEGV;
        int cnt = 0;
        for (int q = lane; q < p; q += 32) {
            float s = 0.f;
            #pragma unroll
            for (int k = 0; k < DM_; k++) s = fmaf(sM[p * DM_ + k], sM[q * DM_ + k], s);
            s = fmaxf(s, 0.f);
            vals[cnt++] = s;
            mx = fmaxf(mx, s);
        }
        #pragma unroll
        for (int off = 16; off; off >>= 1) mx = fmaxf(mx, __shfl_xor_sync(0xffffffffu, mx, off));
        float sum = 0.f;
        for (int c = 0; c < cnt; c++) { vals[c] = expf(vals[c] - mx); sum += vals[c]; }
        #pragma unroll
        for (int off = 16; off; off >>= 1) sum += __shfl_xor_sync(0xffffffffu, sum, off);
        float inv = (p > 0) ? 1.f / sum : 0.f;
        cnt = 0;
        for (int q = lane; q < p; q += 32) sA[p * NN_ + q] = vals[cnt++] * inv;
    }
    __syncthreads();

    for (int e = tid; e < NN_ * NN_; e += 256) outA[e] = sA[e];

    if (tid < 64) {
        int c = 0;
        for (int q = 0; q < 64; q++) c += (sA[tid * NN_ + q] > 1e-15f) ? 1 : 0;
        d1[tid] = rsqrtf(1.f + (float)c);
    } else if (tid < 80) {
        int p = tid;
        int c = 0;
        for (int q = 64; q < 80; q++) c += (sA[p * NN_ + q] > 1e-15f) ? 1 : 0;
        d2[tid - 64] = rsqrtf(1.f + (float)c);
    }
    __syncthreads();

    for (int e = tid; e < 64 * 64; e += 256) {
        int p = e >> 6, q = e & 63;
        g_An11[e] = d1[p] * sA[p * NN_ + q] * d1[q];
    }
    if (tid < 256) {
        int p = tid >> 4, q = tid & 15;
        g_An22[tid] = d2[p] * sA[(64 + p) * NN_ + 64 + q] * d2[q];
    }

    if (tid < 16) {
        int p = 64 + tid;
        float mx = NEGV;
        for (int i = 0; i < 64; i++) {
            float a = sA[p * NN_ + i];
            mx = fmaxf(mx, (a != 0.f) ? a : NEGV);
        }
        float sum = 0.f;
        for (int i = 0; i < 64; i++) {
            float a = sA[p * NN_ + i];
            sum += expf(((a != 0.f) ? a : NEGV) - mx);
        }
        float inv = 1.f / sum;
        unsigned int b0 = 0u, b1 = 0u;
        for (int i = 0; i < 64; i++) {
            float a = sA[p * NN_ + i];
            float v = expf(((a != 0.f) ? a : NEGV) - mx) * inv;
            if (v >= 0.004f) {
                if (i < 32) b0 |= (1u << i);
                else        b1 |= (1u << (i - 32));
            }
        }
        g_AtmBits[tid * 2]     = b0;
        g_AtmBits[tid * 2 + 1] = b1;
    }

    for (int e = tid; e < 50 * 50; e += 256) {
        int p = e / 50, q = e % 50;
        float s = 0.f;
        #pragma unroll 8
        for (int k = 0; k < 64; k++) s = fmaf(Wk[p * 64 + k], Wk[q * 64 + k], s);
        g_theta[e] = s;
    }

    if (tid == 0) {
        float sg = 1.f / (1.f + expf(-smoothing[0]));
        g_coef = -0.5f / (sg * 0.01f);
    }
}

// =====================================================================
// Kernel 1: gather + 3-layer MLP. Paired-k f32x2 + LDS.128 B loads.
// =====================================================================
#define PT 132   // token buffer pitch (mult of 4)
#define PW 132   // weight buffer pitch (mult of 4)

__global__ void __launch_bounds__(256) k_mlp(
    const float* __restrict__ data,
    const float* __restrict__ emb0, const float* __restrict__ emb1, const float* __restrict__ emb2,
    const float* __restrict__ w1, const float* __restrict__ b1,
    const float* __restrict__ w2, const float* __restrict__ b2,
    const float* __restrict__ w3, const float* __restrict__ b3,
    const float* __restrict__ M, const float* __restrict__ Wk,
    const float* __restrict__ smoothing, float* __restrict__ outA)
{
    extern __shared__ float sh[];

    if (blockIdx.x == 640) { do_setup(sh, M, Wk, smoothing, outA); return; }

    float* T0  = sh;                     // 128*PT
    float* T1  = T0 + 128 * PT;          // 128*PT
    float* sW  = T1 + 128 * PT;          // 128*PW
    float* sb1 = sW + 128 * PW;          // 128
    float* sb2 = sb1 + 128;              // 128
    float* sb3 = sb2 + 128;              // 64
    float* sLast = sb3 + 64;             // 128

    const int tid = threadIdx.x;
    const int cx = tid & 15, ry = tid >> 4;
    const int base = blockIdx.x * 128;

    for (int e = tid; e < 128; e += 256) { sb1[e] = b1[e]; sb2[e] = b2[e]; }
    for (int e = tid; e < 64; e += 256) sb3[e] = (e < 50) ? b3[e] : 0.f;
    for (int e = tid; e < 128; e += 256) sLast[e] = data[(size_t)(base + e) * 6 + 5];

    // gather X (128 x 51) token-major into T0
    for (int e = tid; e < 128 * 51; e += 256) {
        int t = e / 51, c = e % 51;
        const float* dr = data + (size_t)(base + t) * 6;
        float v;
        if (c < 32)      { int i0 = (int)dr[0]; v = emb0[i0 * 32 + c]; }
        else if (c < 40) { int i1 = (int)dr[1]; v = emb1[i1 * 8 + (c - 32)]; }
        else if (c < 48) { int i2 = (int)dr[2]; v = emb2[i2 * 8 + (c - 40)]; }
        else             { v = dr[3 + (c - 48)]; }
        T0[t * PT + c] = v;
    }
    // W1 (128 x 51) -> k-major sW[k*PW + o]
    for (int e = tid; e < 128 * 51; e += 256) {
        int o = e / 51, k = e % 51;
        sW[k * PW + o] = w1[e];
    }
    __syncthreads();

    // ---- GEMM1: h1 = relu(X @ W1^T + b1) -> T1  (K=51) ----
    {
        u64 acc[8][4];
        #pragma unroll
        for (int i = 0; i < 8; i++)
            #pragma unroll
            for (int j = 0; j < 4; j++) acc[i][j] = 0ull;
        int k = 0;
        for (; k + 1 < 51; k += 2) {
            ulonglong2 b00 = *reinterpret_cast<const ulonglong2*>(&sW[k * PW + 4 * cx]);
            ulonglong2 b01 = *reinterpret_cast<const ulonglong2*>(&sW[k * PW + 4 * cx + 64]);
            ulonglong2 b10 = *reinterpret_cast<const ulonglong2*>(&sW[(k + 1) * PW + 4 * cx]);
            ulonglong2 b11 = *reinterpret_cast<const ulonglong2*>(&sW[(k + 1) * PW + 4 * cx + 64]);
            #pragma unroll
            for (int i = 0; i < 8; i++) {
                float2 a = *reinterpret_cast<const float2*>(&T0[(ry + 16 * i) * PT + k]);
                u64 a0 = dup2(a.x), a1 = dup2(a.y);
                acc[i][0] = fma2(a0, b00.x, acc[i][0]);
                acc[i][1] = fma2(a0, b00.y, acc[i][1]);
                acc[i][2] = fma2(a0, b01.x, acc[i][2]);
                acc[i][3] = fma2(a0, b01.y, acc[i][3]);
                acc[i][0] = fma2(a1, b10.x, acc[i][0]);
                acc[i][1] = fma2(a1, b10.y, acc[i][1]);
                acc[i][2] = fma2(a1, b11.x, acc[i][2]);
                acc[i][3] = fma2(a1, b11.y, acc[i][3]);
            }
        }
        { // tail k = 50
            ulonglong2 b00 = *reinterpret_cast<const ulonglong2*>(&sW[k * PW + 4 * cx]);
            ulonglong2 b01 = *reinterpret_cast<const ulonglong2*>(&sW[k * PW + 4 * cx + 64]);
            #pragma unroll
            for (int i = 0; i < 8; i++) {
                u64 a0 = dup2(T0[(ry + 16 * i) * PT + k]);
                acc[i][0] = fma2(a0, b00.x, acc[i][0]);
                acc[i][1] = fma2(a0, b00.y, acc[i][1]);
                acc[i][2] = fma2(a0, b01.x, acc[i][2]);
                acc[i][3] = fma2(a0, b01.y, acc[i][3]);
            }
        }
        __syncthreads();
        #pragma unroll
        for (int i = 0; i < 8; i++)
            #pragma unroll
            for (int j = 0; j < 2; j++) {
                int r = ry + 16 * i, c = 4 * cx + 64 * j;
                float4 bias = *reinterpret_cast<const float4*>(&sb1[c]);
                float4 v;
                up2(acc[i][2 * j],     v.x, v.y);
                up2(acc[i][2 * j + 1], v.z, v.w);
                v.x = fmaxf(v.x + bias.x, 0.f);
                v.y = fmaxf(v.y + bias.y, 0.f);
                v.z = fmaxf(v.z + bias.z, 0.f);
                v.w = fmaxf(v.w + bias.w, 0.f);
                *reinterpret_cast<float4*>(&T1[r * PT + c]) = v;
            }
    }
    // W2 (128 x 128) -> k-major
    for (int e = tid; e < 128 * 128; e += 256) {
        int o = e >> 7, k = e & 127;
        sW[k * PW + o] = w2[e];
    }
    __syncthreads();

    // ---- GEMM2: h2 = relu(h1 @ W2^T + b2) -> T0  (K=128) ----
    {
        u64 acc[8][4];
        #pragma unroll
        for (int i = 0; i < 8; i++)
            #pragma unroll
            for (int j = 0; j < 4; j++) acc[i][j] = 0ull;
        for (int k = 0; k < 128; k += 2) {
            ulonglong2 b00 = *reinterpret_cast<const ulonglong2*>(&sW[k * PW + 4 * cx]);
            ulonglong2 b01 = *reinterpret_cast<const ulonglong2*>(&sW[k * PW + 4 * cx + 64]);
            ulonglong2 b10 = *reinterpret_cast<const ulonglong2*>(&sW[(k + 1) * PW + 4 * cx]);
            ulonglong2 b11 = *reinterpret_cast<const ulonglong2*>(&sW[(k + 1) * PW + 4 * cx + 64]);
            #pragma unroll
            for (int i = 0; i < 8; i++) {
                float2 a = *reinterpret_cast<const float2*>(&T1[(ry + 16 * i) * PT + k]);
                u64 a0 = dup2(a.x), a1 = dup2(a.y);
                acc[i][0] = fma2(a0, b00.x, acc[i][0]);
                acc[i][1] = fma2(a0, b00.y, acc[i][1]);
                acc[i][2] = fma2(a0, b01.x, acc[i][2]);
                acc[i][3] = fma2(a0, b01.y, acc[i][3]);
                acc[i][0] = fma2(a1, b10.x, acc[i][0]);
                acc[i][1] = fma2(a1, b10.y, acc[i][1]);
                acc[i][2] = fma2(a1, b11.x, acc[i][2]);
                acc[i][3] = fma2(a1, b11.y, acc[i][3]);
            }
        }
        __syncthreads();
        #pragma unroll
        for (int i = 0; i < 8; i++)
            #pragma unroll
            for (int j = 0; j < 2; j++) {
                int r = ry + 16 * i, c = 4 * cx + 64 * j;
                float4 bias = *reinterpret_cast<const float4*>(&sb2[c]);
                float4 v;
                up2(acc[i][2 * j],     v.x, v.y);
                up2(acc[i][2 * j + 1], v.z, v.w);
                v.x = fmaxf(v.x + bias.x, 0.f);
                v.y = fmaxf(v.y + bias.y, 0.f);
                v.z = fmaxf(v.z + bias.z, 0.f);
                v.w = fmaxf(v.w + bias.w, 0.f);
                *reinterpret_cast<float4*>(&T0[r * PT + c]) = v;
            }
    }
    // W3 (50 x 128, pad rows to 64) -> k-major
    for (int e = tid; e < 64 * 128; e += 256) {
        int o = e >> 7, k = e & 127;
        sW[k * PW + o] = (o < 50) ? w3[o * 128 + k] : 0.f;
    }
    __syncthreads();

    // ---- GEMM3: h3 = h2 @ W3^T + b3 -> g_x  (K=128, 64 cols) ----
    {
        u64 acc[8][2];
        #pragma unroll
        for (int i = 0; i < 8; i++) { acc[i][0] = 0ull; acc[i][1] = 0ull; }
        for (int k = 0; k < 128; k += 2) {
            ulonglong2 b0 = *reinterpret_cast<const ulonglong2*>(&sW[k * PW + 4 * cx]);
            ulonglong2 b1 = *reinterpret_cast<const ulonglong2*>(&sW[(k + 1) * PW + 4 * cx]);
            #pragma unroll
            for (int i = 0; i < 8; i++) {
                float2 a = *reinterpret_cast<const float2*>(&T0[(ry + 16 * i) * PT + k]);
                u64 a0 = dup2(a.x), a1 = dup2(a.y);
                acc[i][0] = fma2(a0, b0.x, acc[i][0]);
                acc[i][1] = fma2(a0, b0.y, acc[i][1]);
                acc[i][0] = fma2(a1, b1.x, acc[i][0]);
                acc[i][1] = fma2(a1, b1.y, acc[i][1]);
            }
        }
        #pragma unroll
        for (int i = 0; i < 8; i++) {
            int r = ry + 16 * i, c = 4 * cx;
            float v0, v1, v2, v3;
            up2(acc[i][0], v0, v1);
            up2(acc[i][1], v2, v3);
            float* go = &g_x[(size_t)(base + r) * CC];
            if (c < 50)     go[c]     = v0 + sb3[c];
            if (c + 1 < 50) go[c + 1] = v1 + sb3[c + 1];
            if (c + 2 < 50) go[c + 2] = v2 + sb3[c + 2];
            if (c + 3 < 50) go[c + 3] = v3 + sb3[c + 3];
        }
        for (int e = tid; e < 128; e += 256)
            g_x[(size_t)(base + e) * CC + 50] = sLast[e];
    }
}

// =====================================================================
// Kernel 2: per-graph pipeline. Paired-k f32x2 + LDS.128, in-place chain.
// =====================================================================
#define PX 54    // xs pitch (even)
#define PZ 68    // gemm buffer pitch (mult of 4)
#define PQ 66    // small 16-row buffer pitch (even)

// C(64x64) = A(64xK, row-major pitch pa) @ B(Kx64, k-major pitch PZ)
// In-place safe: C may alias A or B (sync between accumulate and store).
__device__ __forceinline__ void gemm64_2(const float* __restrict__ A, int pa,
                                         const float* __restrict__ B, int K,
                                         float* __restrict__ C, bool do_relu,
                                         int cx, int ry)
{
    u64 acc[4][2];
    #pragma unroll
    for (int i = 0; i < 4; i++) { acc[i][0] = 0ull; acc[i][1] = 0ull; }
    int k = 0;
    for (; k + 1 < K; k += 2) {
        ulonglong2 b0 = *reinterpret_cast<const ulonglong2*>(&B[k * PZ + 4 * cx]);
        ulonglong2 b1 = *reinterpret_cast<const ulonglong2*>(&B[(k + 1) * PZ + 4 * cx]);
        #pragma unroll
        for (int i = 0; i < 4; i++) {
            float2 a = *reinterpret_cast<const float2*>(&A[(ry + 16 * i) * pa + k]);
            u64 a0 = dup2(a.x), a1 = dup2(a.y);
            acc[i][0] = fma2(a0, b0.x, acc[i][0]);
            acc[i][1] = fma2(a0, b0.y, acc[i][1]);
            acc[i][0] = fma2(a1, b1.x, acc[i][0]);
            acc[i][1] = fma2(a1, b1.y, acc[i][1]);
        }
    }
    if (k < K) {
        ulonglong2 b0 = *reinterpret_cast<const ulonglong2*>(&B[k * PZ + 4 * cx]);
        #pragma unroll
        for (int i = 0; i < 4; i++) {
            u64 a0 = dup2(A[(ry + 16 * i) * pa + k]);
            acc[i][0] = fma2(a0, b0.x, acc[i][0]);
            acc[i][1] = fma2(a0, b0.y, acc[i][1]);
        }
    }
    __syncthreads();
    #pragma unroll
    for (int i = 0; i < 4; i++) {
        float4 v;
        up2(acc[i][0], v.x, v.y);
        up2(acc[i][1], v.z, v.w);
        if (do_relu) {
            v.x = fmaxf(v.x, 0.f); v.y = fmaxf(v.y, 0.f);
            v.z = fmaxf(v.z, 0.f); v.w = fmaxf(v.w, 0.f);
        }
        *reinterpret_cast<float4*>(&C[(ry + 16 * i) * PZ + 4 * cx]) = v;
    }
    __syncthreads();
}

__global__ void __launch_bounds__(256, 2) k_main(
    const float* __restrict__ Wg1a, const float* __restrict__ Wg1b,
    const float* __restrict__ Wg2a, const float* __restrict__ Wg2b,
    float* __restrict__ dout)
{
    extern __shared__ float sh[];
    float* xs    = sh;                    // 80*PX = 4320
    float* WaT   = xs + 80 * PX;          // 51*PZ = 3468 (Wg1a^T then Wg2a^T)
    float* An11s = WaT + 51 * PZ;         // 64*64 = 4096
    float* WbT   = An11s + 64 * 64;       // 64*PZ (Wg1b^T then theta)
    float* B1    = WbT + 64 * PZ;         // 64*PZ
    float* B2    = B1 + 64 * PZ;          // 64*PZ
    float* z3    = B2 + 64 * PZ;          // 16*PQ
    float* t2b   = z3 + 16 * PQ;          // 16*PQ
    float* Ls    = t2b + 16 * PQ;         // 16*PQ
    float* An22s = Ls + 16 * PQ;          // 16*17
    float* Wg2bs = An22s + 16 * 17;       // 64
    float* yhv   = Wg2bs + 64;            // 16
    float* z4v   = yhv + 16;              // 16
    float* sqv   = z4v + 16;              // 80
    unsigned int* AtmB = (unsigned int*)(sqv + 80); // 32

    const int tid = threadIdx.x;
    const int tx = tid & 15, ty = tid >> 4;   // also (cx, ry) for gemms
    const int b = blockIdx.x;
    const float* gx = g_x + (size_t)b * NN_ * CC;

    // -------- load phase --------
    for (int e = tid; e < 80 * 51; e += 256) xs[(e / 51) * PX + e % 51] = gx[e];
    for (int e = tid; e < 64 * 51; e += 256) {
        int o = e / 51, k = e % 51;
        WaT[k * PZ + o] = Wg1a[e];
    }
    for (int e = tid; e < 64 * 64; e += 256) {
        int o = e >> 6, k = e & 63;
        WbT[k * PZ + o] = (o < 50) ? Wg1b[o * 64 + k] : 0.f;
    }
    for (int e = tid; e < 64 * 64; e += 256) An11s[e] = g_An11[e];
    if (tid < 256) An22s[(tid >> 4) * 17 + (tid & 15)] = g_An22[tid];
    if (tid < 32) AtmB[tid] = g_AtmBits[tid];
    if (tid >= 32 && tid < 96) Wg2bs[tid - 32] = Wg2b[tid - 32];
    __syncthreads();

    // -------- gcnn1 (in-place ping-pong) --------
    gemm64_2(xs, PX, WaT, 51, B1, false, tx, ty);     // z1 = sg1 @ Wg1a^T
    // WaT free: reload Wg2a^T
    for (int e = tid; e < 64 * 51; e += 256) {
        int o = e / 51, k = e % 51;
        WaT[k * PZ + o] = Wg2a[e];
    }
    gemm64_2(An11s, 64, B1, 64, B1, true, tx, ty);    // t1 = relu(An11 @ z1)  (in-place)
    gemm64_2(B1, PZ, WbT, 64, B1, false, tx, ty);     // z2 = t1 @ Wg1b^T      (in-place)
    // WbT free: reload theta (k-major, 50 rows)
    for (int e = tid; e < 50 * 64; e += 256) {
        int k = e >> 6, q = e & 63;
        WbT[k * PZ + q] = (q < 50) ? g_theta[k * 50 + q] : 0.f;
    }
    gemm64_2(An11s, 64, B1, 64, B2, false, tx, ty);   // x1 = An11 @ z2 -> B2
    gemm64_2(B2, PZ, WbT, 50, B1, false, tx, ty);     // u  = x1 @ theta -> B1

    // -------- V = xf @ theta (16x64) -> z3 --------
    {
        u64 acc[2] = {0ull, 0ull};
        for (int k = 0; k < 50; k++) {
            u64 ad = dup2(xs[(64 + ty) * PX + k]);
            #pragma unroll
            for (int j = 0; j < 2; j++)
                acc[j] = fma2(ad, *reinterpret_cast<const u64*>(&WbT[k * PZ + 2 * tx + 32 * j]), acc[j]);
        }
        __syncthreads();
        #pragma unroll
        for (int j = 0; j < 2; j++) {
            float v0, v1; up2(acc[j], v0, v1);
            int c = 2 * tx + 32 * j;
            z3[ty * PQ + c] = v0;
            z3[ty * PQ + c + 1] = v1;
        }
        __syncthreads();
    }

    // -------- q[j][i] = (xp_i - xf_j) . (u_i - v_j); masked logits -> Ls --------
    {
        float cf = g_coef;
        float acc[4] = {0.f, 0.f, 0.f, 0.f};
        for (int k = 0; k < 50; k++) {
            float xfk = xs[(64 + ty) * PX + k];
            float vk  = z3[ty * PQ + k];
            #pragma unroll
            for (int j = 0; j < 4; j++) {
                int i = tx + 16 * j;
                acc[j] = fmaf(B2[i * PZ + k] - xfk, B1[i * PZ + k] - vk, acc[j]);
            }
        }
        unsigned int m0 = AtmB[ty * 2], m1 = AtmB[ty * 2 + 1];
        __syncthreads();
        #pragma unroll
        for (int j = 0; j < 4; j++) {
            int i = tx + 16 * j;
            bool on = (i < 32) ? ((m0 >> i) & 1u) : ((m1 >> (i - 32)) & 1u);
            Ls[ty * PQ + i] = on ? (cf * acc[j]) : NEGV;
        }
        __syncthreads();
    }

    // -------- softmax over j --------
    if (tid < 64) {
        int i = tid;
        float m = NEGV;
        for (int j = 0; j < 16; j++) m = fmaxf(m, Ls[j * PQ + i]);
        float s = 0.f;
        for (int j = 0; j < 16; j++) {
            float e = expf(Ls[j * PQ + i] - m);
            Ls[j * PQ + i] = e;
            s += e;
        }
        float inv = 1.f / s;
        for (int j = 0; j < 16; j++) Ls[j * PQ + i] *= inv;
    }
    __syncthreads();

    // -------- yh, splice --------
    if (tid < 16) {
        float s = 0.f;
        for (int i = 0; i < 64; i++) s = fmaf(Ls[tid * PQ + i], xs[i * PX + 50], s);
        yhv[tid] = s;
    }
    __syncthreads();
    if (tid < 16) xs[(64 + tid) * PX + 50] = yhv[tid];
    __syncthreads();

    // -------- gcnn2 (WaT holds Wg2a^T) --------
    {
        u64 acc[2] = {0ull, 0ull};
        for (int k = 0; k < 51; k++) {
            u64 ad = dup2(xs[(64 + ty) * PX + k]);
            #pragma unroll
            for (int j = 0; j < 2; j++)
                acc[j] = fma2(ad, *reinterpret_cast<const u64*>(&WaT[k * PZ + 2 * tx + 32 * j]), acc[j]);
        }
        __syncthreads();
        #pragma unroll
        for (int j = 0; j < 2; j++) {
            float v0, v1; up2(acc[j], v0, v1);
            int c = 2 * tx + 32 * j;
            z3[ty * PQ + c] = v0;
            z3[ty * PQ + c + 1] = v1;
        }
        __syncthreads();
    }
    {
        u64 acc[2] = {0ull, 0ull};
        for (int q = 0; q < 16; q++) {
            u64 ad = dup2(An22s[ty * 17 + q]);
            #pragma unroll
            for (int j = 0; j < 2; j++)
                acc[j] = fma2(ad, *reinterpret_cast<const u64*>(&z3[q * PQ + 2 * tx + 32 * j]), acc[j]);
        }
        __syncthreads();
        #pragma unroll
        for (int j = 0; j < 2; j++) {
            float v0, v1; up2(acc[j], v0, v1);
            int c = 2 * tx + 32 * j;
            t2b[ty * PQ + c]     = fmaxf(v0, 0.f);
            t2b[ty * PQ + c + 1] = fmaxf(v1, 0.f);
        }
        __syncthreads();
    }
    if (tid < 16) {
        float s = 0.f;
        for (int c = 0; c < 64; c++) s = fmaf(t2b[tid * PQ + c], Wg2bs[c], s);
        z4v[tid] = s;
    }
    __syncthreads();
    if (tid < 16) {
        float s = 0.f;
        for (int q = 0; q < 16; q++) s = fmaf(An22s[tid * 17 + q], z4v[q], s);
        dout[b * 16 + tid] = s;
    }

    // -------- pairwise dist on xc (80x51) --------
    if (tid < 80) {
        float s = 0.f;
        for (int c = 0; c < 51; c++) {
            float v = xs[tid * PX + c];
            s = fmaf(v, v, s);
        }
        sqv[tid] = s;
    }
    __syncthreads();
    {
        float acc[5][5];
        #pragma unroll
        for (int i = 0; i < 5; i++)
            #pragma unroll
            for (int j = 0; j < 5; j++) acc[i][j] = 0.f;
        for (int k = 0; k < 51; k++) {
            float a[5], bb[5];
            #pragma unroll
            for (int i = 0; i < 5; i++) a[i] = xs[(ty * 5 + i) * PX + k];
            #pragma unroll
            for (int j = 0; j < 5; j++) bb[j] = xs[(tx * 5 + j) * PX + k];
            #pragma unroll
            for (int i = 0; i < 5; i++)
                #pragma unroll
                for (int j = 0; j < 5; j++) acc[i][j] = fmaf(a[i], bb[j], acc[i][j]);
        }
        float* dd = dout + DIST_OFF + (size_t)b * 6400;
        #pragma unroll
        for (int i = 0; i < 5; i++)
            #pragma unroll
            for (int j = 0; j < 5; j++) {
                int n = ty * 5 + i, m = tx * 5 + j;
                float d2 = sqv[n] + sqv[m] - 2.f * acc[i][j];
                dd[n * 80 + m] = (d2 > 0.f) ? sqrtf(d2) : 0.f;
            }
    }
}

// =====================================================================
// launcher
// =====================================================================
extern "C" void kernel_launch(void* const* d_in, const int* in_sizes, int n_in,
                              void* d_out, int out_size)
{
    const float* data  = (const float*)d_in[0];
    const float* emb0  = (const float*)d_in[1];
    const float* emb1  = (const float*)d_in[2];
    const float* emb2  = (const float*)d_in[3];
    const float* w1    = (const float*)d_in[4];
    const float* b1    = (const float*)d_in[5];
    const float* w2    = (const float*)d_in[6];
    const float* b2    = (const float*)d_in[7];
    const float* w3    = (const float*)d_in[8];
    const float* b3    = (const float*)d_in[9];
    const float* M     = (const float*)d_in[10];
    const float* Wg1a  = (const float*)d_in[11];
    const float* Wg1b  = (const float*)d_in[12];
    const float* Wk    = (const float*)d_in[13];
    const float* smoothing = (const float*)d_in[14];
    const float* Wg2a  = (const float*)d_in[15];
    const float* Wg2b  = (const float*)d_in[16];
    float* out = (float*)d_out;

    const int SMEM_MLP  = (3 * 128 * PT + 128 + 128 + 64 + 128) * 4;
    const int SMEM_MAIN = (80 * PX + 51 * PZ + 64 * 64 + 3 * 64 * PZ + 3 * 16 * PQ +
                           16 * 17 + 64 + 16 + 16 + 80 + 32) * 4;

    cudaFuncSetAttribute(k_mlp, cudaFuncAttributeMaxDynamicSharedMemorySize, SMEM_MLP);
    cudaFuncSetAttribute(k_main, cudaFuncAttributeMaxDynamicSharedMemorySize, SMEM_MAIN);

    k_mlp<<<641, 256, SMEM_MLP>>>(data, emb0, emb1, emb2, w1, b1, w2, b2, w3, b3,
                                  M, Wk, smoothing, out + A_OFF);
    k_main<<<1024, 256, SMEM_MAIN>>>(Wg1a, Wg1b, Wg2a, Wg2b, out);
}

// round 6
// speedup vs baseline: 1.6547x; 1.1020x over previous
#include <cuda_runtime.h>
#include <math.h>

// ---------------- problem constants ----------------
#define BB    1024
#define NN_   80
#define CC    51     // OUTP
#define DM_   26
#define NEGV  -1e30f

#define DIST_OFF 16384
#define A_OFF    (16384 + 1024*6400)

typedef unsigned long long u64;

// ---------------- f32x2 packed helpers ----------------
__device__ __forceinline__ u64 pk2(float lo, float hi) {
    u64 r; asm("mov.b64 %0,{%1,%2};" : "=l"(r) : "f"(lo), "f"(hi)); return r;
}
__device__ __forceinline__ u64 dup2(float v) { return pk2(v, v); }
__device__ __forceinline__ void up2(u64 v, float& a, float& b) {
    asm("mov.b64 {%0,%1},%2;" : "=f"(a), "=f"(b) : "l"(v));
}
__device__ __forceinline__ u64 fma2(u64 a, u64 b, u64 c) {
    u64 d; asm("fma.rn.f32x2 %0,%1,%2,%3;" : "=l"(d) : "l"(a), "l"(b), "l"(c)); return d;
}

// ---------------- device scratch / prepped constants ----------------
__device__ float g_x[BB * NN_ * CC];
__device__ float g_An11[64 * 64];
__device__ float g_An22[16 * 16];
__device__ unsigned int g_AtmBits[32];
__device__ float g_Wg1aT[51 * 64];   // [k][o]
__device__ float g_Wg2aT[51 * 64];   // [k][o]
__device__ float g_Wg1bT[64 * 64];   // [h][o2], o2>=50 zero
__device__ float g_thetaB[50 * 64];  // [c][r], r>=50 zero
__device__ float g_coef;

// =====================================================================
// setup work: executed by one extra block of k_mlp (256 threads)
// =====================================================================
__device__ void do_setup(float* sh,
                         const float* __restrict__ M, const float* __restrict__ Wk,
                         const float* __restrict__ smoothing,
                         const float* __restrict__ Wg1a, const float* __restrict__ Wg1b,
                         const float* __restrict__ Wg2a,
                         float* __restrict__ outA)
{
    float* sM = sh;                 // 80*26
    float* sA = sM + NN_ * DM_;     // 80*80
    float* d1 = sA + NN_ * NN_;     // 64
    float* d2 = d1 + 64;            // 16
    const int tid = threadIdx.x;
    const int lane = tid & 31, warp = tid >> 5;

    for (int e = tid; e < NN_ * DM_; e += 256) sM[e] = M[e];
    for (int e = tid; e < NN_ * NN_; e += 256) sA[e] = 0.f;
    __syncthreads();

    for (int p = warp; p < NN_; p += 8) {
        float vals[3];
        float mx = NEGV;
        int cnt = 0;
        for (int q = lane; q < p; q += 32) {
            float s = 0.f;
            #pragma unroll
            for (int k = 0; k < DM_; k++) s = fmaf(sM[p * DM_ + k], sM[q * DM_ + k], s);
            s = fmaxf(s, 0.f);
            vals[cnt++] = s;
            mx = fmaxf(mx, s);
        }
        #pragma unroll
        for (int off = 16; off; off >>= 1) mx = fmaxf(mx, __shfl_xor_sync(0xffffffffu, mx, off));
        float sum = 0.f;
        for (int c = 0; c < cnt; c++) { vals[c] = expf(vals[c] - mx); sum += vals[c]; }
        #pragma unroll
        for (int off = 16; off; off >>= 1) sum += __shfl_xor_sync(0xffffffffu, sum, off);
        float inv = (p > 0) ? 1.f / sum : 0.f;
        cnt = 0;
        for (int q = lane; q < p; q += 32) sA[p * NN_ + q] = vals[cnt++] * inv;
    }
    __syncthreads();

    for (int e = tid; e < NN_ * NN_; e += 256) outA[e] = sA[e];

    if (tid < 64) {
        int c = 0;
        for (int q = 0; q < 64; q++) c += (sA[tid * NN_ + q] > 1e-15f) ? 1 : 0;
        d1[tid] = rsqrtf(1.f + (float)c);
    } else if (tid < 80) {
        int p = tid;
        int c = 0;
        for (int q = 64; q < 80; q++) c += (sA[p * NN_ + q] > 1e-15f) ? 1 : 0;
        d2[tid - 64] = rsqrtf(1.f + (float)c);
    }
    __syncthreads();

    for (int e = tid; e < 64 * 64; e += 256) {
        int p = e >> 6, q = e & 63;
        g_An11[e] = d1[p] * sA[p * NN_ + q] * d1[q];
    }
    if (tid < 256) {
        int p = tid >> 4, q = tid & 15;
        g_An22[tid] = d2[p] * sA[(64 + p) * NN_ + 64 + q] * d2[q];
    }

    if (tid < 16) {
        int p = 64 + tid;
        float mx = NEGV;
        for (int i = 0; i < 64; i++) {
            float a = sA[p * NN_ + i];
            mx = fmaxf(mx, (a != 0.f) ? a : NEGV);
        }
        float sum = 0.f;
        for (int i = 0; i < 64; i++) {
            float a = sA[p * NN_ + i];
            sum += expf(((a != 0.f) ? a : NEGV) - mx);
        }
        float inv = 1.f / sum;
        unsigned int b0 = 0u, b1 = 0u;
        for (int i = 0; i < 64; i++) {
            float a = sA[p * NN_ + i];
            float v = expf(((a != 0.f) ? a : NEGV) - mx) * inv;
            if (v >= 0.004f) {
                if (i < 32) b0 |= (1u << i);
                else        b1 |= (1u << (i - 32));
            }
        }
        g_AtmBits[tid * 2]     = b0;
        g_AtmBits[tid * 2 + 1] = b1;
    }

    // theta (padded cols) = Wk @ Wk^T
    for (int e = tid; e < 50 * 64; e += 256) {
        int c = e >> 6, r = e & 63;
        float s = 0.f;
        if (r < 50) {
            #pragma unroll 8
            for (int k = 0; k < 64; k++) s = fmaf(Wk[c * 64 + k], Wk[r * 64 + k], s);
        }
        g_thetaB[e] = s;
    }

    // transposed weights for k_main's B-operands
    for (int e = tid; e < 51 * 64; e += 256) {
        int k = e >> 6, o = e & 63;
        g_Wg1aT[e] = Wg1a[o * 51 + k];
        g_Wg2aT[e] = Wg2a[o * 51 + k];
    }
    for (int e = tid; e < 64 * 64; e += 256) {
        int h = e >> 6, o = e & 63;
        g_Wg1bT[e] = (o < 50) ? Wg1b[o * 64 + h] : 0.f;
    }

    if (tid == 0) {
        float sg = 1.f / (1.f + expf(-smoothing[0]));
        g_coef = -0.5f / (sg * 0.01f);
    }
}

// =====================================================================
// Kernel 1: gather + 3-layer MLP. Feature-major token buffer (in-place),
// weights as global A-operands (broadcast). 64 tokens/block, 3 CTAs/SM.
// =====================================================================
#define PT 68   // token buffer pitch (64 tokens + pad, mult of 4)

__global__ void __launch_bounds__(256, 3) k_mlp(
    const float* __restrict__ data,
    const float* __restrict__ emb0, const float* __restrict__ emb1, const float* __restrict__ emb2,
    const float* __restrict__ w1, const float* __restrict__ b1,
    const float* __restrict__ w2, const float* __restrict__ b2,
    const float* __restrict__ w3, const float* __restrict__ b3,
    const float* __restrict__ M, const float* __restrict__ Wk,
    const float* __restrict__ smoothing,
    const float* __restrict__ Wg1a, const float* __restrict__ Wg1b,
    const float* __restrict__ Wg2a,
    float* __restrict__ outA)
{
    extern __shared__ float sh[];

    if (blockIdx.x == 1280) {
        do_setup(sh, M, Wk, smoothing, Wg1a, Wg1b, Wg2a, outA);
        return;
    }

    float* T     = sh;              // 128 * PT (feature-major: [feat][token])
    float* sLast = T + 128 * PT;    // 64

    const int tid = threadIdx.x;
    const int cx = tid & 15, ry = tid >> 4;   // cx -> 4 tokens, ry -> rows
    const int base = blockIdx.x * 64;

    if (tid < 64) sLast[tid] = data[(size_t)(base + tid) * 6 + 5];

    // gather X^T (51 x 64): T[c][t]
    for (int e = tid; e < 51 * 64; e += 256) {
        int c = e >> 6, t = e & 63;
        const float* dr = data + (size_t)(base + t) * 6;
        float v;
        if (c < 32)      { int i0 = (int)dr[0]; v = emb0[i0 * 32 + c]; }
        else if (c < 40) { int i1 = (int)dr[1]; v = emb1[i1 * 8 + (c - 32)]; }
        else if (c < 48) { int i2 = (int)dr[2]; v = emb2[i2 * 8 + (c - 40)]; }
        else             { v = dr[3 + (c - 48)]; }
        T[c * PT + t] = v;
    }
    __syncthreads();

    // ---- GEMM1: h1[o][t] = relu(sum_k w1[o][k] * T[k][t] + b1[o]) ----
    // 128 rows, 64 cols; thread: 8 rows x 4 cols. A scalar global (bcast).
    {
        u64 acc[8][2];
        #pragma unroll
        for (int i = 0; i < 8; i++) { acc[i][0] = 0ull; acc[i][1] = 0ull; }
        for (int k = 0; k < 51; k++) {
            ulonglong2 bv = *reinterpret_cast<const ulonglong2*>(&T[k * PT + 4 * cx]);
            #pragma unroll
            for (int i = 0; i < 8; i++) {
                u64 ad = dup2(__ldg(&w1[(ry + 16 * i) * 51 + k]));
                acc[i][0] = fma2(ad, bv.x, acc[i][0]);
                acc[i][1] = fma2(ad, bv.y, acc[i][1]);
            }
        }
        __syncthreads();
        #pragma unroll
        for (int i = 0; i < 8; i++) {
            int o = ry + 16 * i;
            float bo = __ldg(&b1[o]);
            float4 v;
            up2(acc[i][0], v.x, v.y);
            up2(acc[i][1], v.z, v.w);
            v.x = fmaxf(v.x + bo, 0.f); v.y = fmaxf(v.y + bo, 0.f);
            v.z = fmaxf(v.z + bo, 0.f); v.w = fmaxf(v.w + bo, 0.f);
            *reinterpret_cast<float4*>(&T[o * PT + 4 * cx]) = v;
        }
        __syncthreads();
    }

    // ---- GEMM2: h2[o][t] = relu(sum_k w2[o][k] * T[k][t] + b2[o]) ----
    // K=128; A prefetch LDG.128 per 4k.
    {
        u64 acc[8][2];
        #pragma unroll
        for (int i = 0; i < 8; i++) { acc[i][0] = 0ull; acc[i][1] = 0ull; }
        #pragma unroll 2
        for (int k0 = 0; k0 < 128; k0 += 4) {
            float4 ap[8];
            #pragma unroll
            for (int i = 0; i < 8; i++)
                ap[i] = *reinterpret_cast<const float4*>(&w2[(ry + 16 * i) * 128 + k0]);
            #pragma unroll
            for (int kk = 0; kk < 4; kk++) {
                ulonglong2 bv = *reinterpret_cast<const ulonglong2*>(&T[(k0 + kk) * PT + 4 * cx]);
                #pragma unroll
                for (int i = 0; i < 8; i++) {
                    float av = (kk == 0) ? ap[i].x : (kk == 1) ? ap[i].y : (kk == 2) ? ap[i].z : ap[i].w;
                    u64 ad = dup2(av);
                    acc[i][0] = fma2(ad, bv.x, acc[i][0]);
                    acc[i][1] = fma2(ad, bv.y, acc[i][1]);
                }
            }
        }
        __syncthreads();
        #pragma unroll
        for (int i = 0; i < 8; i++) {
            int o = ry + 16 * i;
            float bo = __ldg(&b2[o]);
            float4 v;
            up2(acc[i][0], v.x, v.y);
            up2(acc[i][1], v.z, v.w);
            v.x = fmaxf(v.x + bo, 0.f); v.y = fmaxf(v.y + bo, 0.f);
            v.z = fmaxf(v.z + bo, 0.f); v.w = fmaxf(v.w + bo, 0.f);
            *reinterpret_cast<float4*>(&T[o * PT + 4 * cx]) = v;
        }
        __syncthreads();
    }

    // ---- GEMM3: h3[o][t] = sum_k w3[o][k] * T[k][t] + b3[o], o<50 -> g_x ----
    {
        u64 acc[4][2];
        #pragma unroll
        for (int i = 0; i < 4; i++) { acc[i][0] = 0ull; acc[i][1] = 0ull; }
        #pragma unroll 2
        for (int k0 = 0; k0 < 128; k0 += 4) {
            float4 ap[4];
            #pragma unroll
            for (int i = 0; i < 4; i++) {
                int o = ry + 16 * i;
                ap[i] = (o < 50) ? *reinterpret_cast<const float4*>(&w3[o * 128 + k0])
                                 : make_float4(0.f, 0.f, 0.f, 0.f);
            }
            #pragma unroll
            for (int kk = 0; kk < 4; kk++) {
                ulonglong2 bv = *reinterpret_cast<const ulonglong2*>(&T[(k0 + kk) * PT + 4 * cx]);
                #pragma unroll
                for (int i = 0; i < 4; i++) {
                    float av = (kk == 0) ? ap[i].x : (kk == 1) ? ap[i].y : (kk == 2) ? ap[i].z : ap[i].w;
                    u64 ad = dup2(av);
                    acc[i][0] = fma2(ad, bv.x, acc[i][0]);
                    acc[i][1] = fma2(ad, bv.y, acc[i][1]);
                }
            }
        }
        #pragma unroll
        for (int i = 0; i < 4; i++) {
            int o = ry + 16 * i;
            if (o < 50) {
                float bo = __ldg(&b3[o]);
                float v0, v1, v2, v3;
                up2(acc[i][0], v0, v1);
                up2(acc[i][1], v2, v3);
                int t = base + 4 * cx;
                g_x[(size_t)(t + 0) * CC + o] = v0 + bo;
                g_x[(size_t)(t + 1) * CC + o] = v1 + bo;
                g_x[(size_t)(t + 2) * CC + o] = v2 + bo;
                g_x[(size_t)(t + 3) * CC + o] = v3 + bo;
            }
        }
        if (tid < 64) g_x[(size_t)(base + tid) * CC + 50] = sLast[tid];
    }
}

// =====================================================================
// Kernel 2: per-graph pipeline. Constants from global, data in smem.
// 64.6 KB smem -> 3 CTAs/SM.
// =====================================================================
#define PXM 52   // xs pitch (even)
#define PZB 68   // big buffer pitch (mult of 4)
#define PQ  66   // small 16-row buffer pitch (even)

// C(64x64) = A(64xK smem, pitch pa) @ B(Kx64 global, ld 64). C may alias A.
__device__ __forceinline__ void gemm_AS_BG(const float* As, int pa,
                                           const float* __restrict__ Bg, int K,
                                           float* Cs, bool do_relu, int cx, int ry)
{
    u64 acc[4][2];
    #pragma unroll
    for (int i = 0; i < 4; i++) { acc[i][0] = 0ull; acc[i][1] = 0ull; }
    int k = 0;
    #pragma unroll 4
    for (; k + 1 < K; k += 2) {
        ulonglong2 b0 = *reinterpret_cast<const ulonglong2*>(Bg + k * 64 + 4 * cx);
        ulonglong2 b1 = *reinterpret_cast<const ulonglong2*>(Bg + (k + 1) * 64 + 4 * cx);
        #pragma unroll
        for (int i = 0; i < 4; i++) {
            float2 a = *reinterpret_cast<const float2*>(As + (ry + 16 * i) * pa + k);
            u64 a0 = dup2(a.x), a1 = dup2(a.y);
            acc[i][0] = fma2(a0, b0.x, acc[i][0]);
            acc[i][1] = fma2(a0, b0.y, acc[i][1]);
            acc[i][0] = fma2(a1, b1.x, acc[i][0]);
            acc[i][1] = fma2(a1, b1.y, acc[i][1]);
        }
    }
    if (k < K) {
        ulonglong2 b0 = *reinterpret_cast<const ulonglong2*>(Bg + k * 64 + 4 * cx);
        #pragma unroll
        for (int i = 0; i < 4; i++) {
            u64 a0 = dup2(As[(ry + 16 * i) * pa + k]);
            acc[i][0] = fma2(a0, b0.x, acc[i][0]);
            acc[i][1] = fma2(a0, b0.y, acc[i][1]);
        }
    }
    __syncthreads();
    #pragma unroll
    for (int i = 0; i < 4; i++) {
        float4 v;
        up2(acc[i][0], v.x, v.y);
        up2(acc[i][1], v.z, v.w);
        if (do_relu) {
            v.x = fmaxf(v.x, 0.f); v.y = fmaxf(v.y, 0.f);
            v.z = fmaxf(v.z, 0.f); v.w = fmaxf(v.w, 0.f);
        }
        *reinterpret_cast<float4*>(&Cs[(ry + 16 * i) * PZB + 4 * cx]) = v;
    }
    __syncthreads();
}

// C(64x64) = A(64x64 global bcast, ld 64) @ B(64x64 smem, pitch PZB). C may alias B.
__device__ __forceinline__ void gemm_AG_BS(const float* __restrict__ Ag,
                                           const float* Bs,
                                           float* Cs, bool do_relu, int cx, int ry)
{
    u64 acc[4][2];
    #pragma unroll
    for (int i = 0; i < 4; i++) { acc[i][0] = 0ull; acc[i][1] = 0ull; }
    #pragma unroll 4
    for (int k = 0; k < 64; k += 2) {
        ulonglong2 b0 = *reinterpret_cast<const ulonglong2*>(&Bs[k * PZB + 4 * cx]);
        ulonglong2 b1 = *reinterpret_cast<const ulonglong2*>(&Bs[(k + 1) * PZB + 4 * cx]);
        #pragma unroll
        for (int i = 0; i < 4; i++) {
            float2 a = *reinterpret_cast<const float2*>(Ag + (ry + 16 * i) * 64 + k);
            u64 a0 = dup2(a.x), a1 = dup2(a.y);
            acc[i][0] = fma2(a0, b0.x, acc[i][0]);
            acc[i][1] = fma2(a0, b0.y, acc[i][1]);
            acc[i][0] = fma2(a1, b1.x, acc[i][0]);
            acc[i][1] = fma2(a1, b1.y, acc[i][1]);
        }
    }
    __syncthreads();
    #pragma unroll
    for (int i = 0; i < 4; i++) {
        float4 v;
        up2(acc[i][0], v.x, v.y);
        up2(acc[i][1], v.z, v.w);
        if (do_relu) {
            v.x = fmaxf(v.x, 0.f); v.y = fmaxf(v.y, 0.f);
            v.z = fmaxf(v.z, 0.f); v.w = fmaxf(v.w, 0.f);
        }
        *reinterpret_cast<float4*>(&Cs[(ry + 16 * i) * PZB + 4 * cx]) = v;
    }
    __syncthreads();
}

__global__ void __launch_bounds__(256, 3) k_main(
    const float* __restrict__ Wg2b,
    float* __restrict__ dout)
{
    extern __shared__ float sh[];
    float* xs  = sh;                 // 80*PXM = 4160
    float* B1  = xs + 80 * PXM;      // 64*PZB
    float* B2  = B1 + 64 * PZB;      // 64*PZB
    float* z3  = B2 + 64 * PZB;      // 16*PQ
    float* t2b = z3 + 16 * PQ;       // 16*PQ
    float* Ls  = t2b + 16 * PQ;      // 16*PQ
    float* yhv = Ls + 16 * PQ;       // 16
    float* z4v = yhv + 16;           // 16
    float* sqv = z4v + 16;           // 80

    const int tid = threadIdx.x;
    const int tx = tid & 15, ty = tid >> 4;
    const int b = blockIdx.x;
    const float* gx = g_x + (size_t)b * NN_ * CC;

    // -------- load per-graph features --------
    for (int e = tid; e < 80 * 51; e += 256) xs[(e / 51) * PXM + e % 51] = gx[e];
    __syncthreads();

    // -------- gcnn1 chain --------
    gemm_AS_BG(xs, PXM, g_Wg1aT, 51, B1, false, tx, ty);   // z1
    gemm_AG_BS(g_An11, B1, B1, true, tx, ty);              // t1 = relu(An11 @ z1)
    gemm_AS_BG(B1, PZB, g_Wg1bT, 64, B1, false, tx, ty);   // z2
    gemm_AG_BS(g_An11, B1, B2, false, tx, ty);             // x1 -> B2
    gemm_AS_BG(B2, PZB, g_thetaB, 50, B1, false, tx, ty);  // u  -> B1

    // -------- v = xf @ theta (16x64) -> z3 --------
    {
        u64 acc[2] = {0ull, 0ull};
        for (int k = 0; k < 50; k++) {
            u64 ad = dup2(xs[(64 + ty) * PXM + k]);
            acc[0] = fma2(ad, *reinterpret_cast<const u64*>(&g_thetaB[k * 64 + 2 * tx]), acc[0]);
            acc[1] = fma2(ad, *reinterpret_cast<const u64*>(&g_thetaB[k * 64 + 2 * tx + 32]), acc[1]);
        }
        __syncthreads();
        #pragma unroll
        for (int j = 0; j < 2; j++) {
            float v0, v1; up2(acc[j], v0, v1);
            int c = 2 * tx + 32 * j;
            z3[ty * PQ + c] = v0;
            z3[ty * PQ + c + 1] = v1;
        }
        __syncthreads();
    }

    // -------- q[j][i] = (xp_i - xf_j) . (u_i - v_j); masked logits -> Ls --------
    {
        float cf = g_coef;
        float acc[4] = {0.f, 0.f, 0.f, 0.f};
        for (int k = 0; k < 50; k++) {
            float xfk = xs[(64 + ty) * PXM + k];
            float vk  = z3[ty * PQ + k];
            #pragma unroll
            for (int j = 0; j < 4; j++) {
                int i = tx + 16 * j;
                acc[j] = fmaf(B2[i * PZB + k] - xfk, B1[i * PZB + k] - vk, acc[j]);
            }
        }
        unsigned int m0 = __ldg(&g_AtmBits[ty * 2]);
        unsigned int m1 = __ldg(&g_AtmBits[ty * 2 + 1]);
        __syncthreads();
        #pragma unroll
        for (int j = 0; j < 4; j++) {
            int i = tx + 16 * j;
            bool on = (i < 32) ? ((m0 >> i) & 1u) : ((m1 >> (i - 32)) & 1u);
            Ls[ty * PQ + i] = on ? (cf * acc[j]) : NEGV;
        }
        __syncthreads();
    }

    // -------- softmax over j --------
    if (tid < 64) {
        int i = tid;
        float m = NEGV;
        for (int j = 0; j < 16; j++) m = fmaxf(m, Ls[j * PQ + i]);
        float s = 0.f;
        for (int j = 0; j < 16; j++) {
            float e = expf(Ls[j * PQ + i] - m);
            Ls[j * PQ + i] = e;
            s += e;
        }
        float inv = 1.f / s;
        for (int j = 0; j < 16; j++) Ls[j * PQ + i] *= inv;
    }
    __syncthreads();

    // -------- yh, splice --------
    if (tid < 16) {
        float s = 0.f;
        for (int i = 0; i < 64; i++) s = fmaf(Ls[tid * PQ + i], xs[i * PXM + 50], s);
        yhv[tid] = s;
    }
    __syncthreads();
    if (tid < 16) xs[(64 + tid) * PXM + 50] = yhv[tid];
    __syncthreads();

    // -------- gcnn2 --------
    {   // z3g[j][o] = x2_j . Wg2a_o
        u64 acc[2] = {0ull, 0ull};
        for (int k = 0; k < 51; k++) {
            u64 ad = dup2(xs[(64 + ty) * PXM + k]);
            acc[0] = fma2(ad, *reinterpret_cast<const u64*>(&g_Wg2aT[k * 64 + 2 * tx]), acc[0]);
            acc[1] = fma2(ad, *reinterpret_cast<const u64*>(&g_Wg2aT[k * 64 + 2 * tx + 32]), acc[1]);
        }
        __syncthreads();
        #pragma unroll
        for (int j = 0; j < 2; j++) {
            float v0, v1; up2(acc[j], v0, v1);
            int c = 2 * tx + 32 * j;
            z3[ty * PQ + c] = v0;
            z3[ty * PQ + c + 1] = v1;
        }
        __syncthreads();
    }
    {   // t2 = relu(An22 @ z3g)
        u64 acc[2] = {0ull, 0ull};
        for (int q = 0; q < 16; q++) {
            u64 ad = dup2(__ldg(&g_An22[ty * 16 + q]));
            acc[0] = fma2(ad, *reinterpret_cast<const u64*>(&z3[q * PQ + 2 * tx]), acc[0]);
            acc[1] = fma2(ad, *reinterpret_cast<const u64*>(&z3[q * PQ + 2 * tx + 32]), acc[1]);
        }
        __syncthreads();
        #pragma unroll
        for (int j = 0; j < 2; j++) {
            float v0, v1; up2(acc[j], v0, v1);
            int c = 2 * tx + 32 * j;
            t2b[ty * PQ + c]     = fmaxf(v0, 0.f);
            t2b[ty * PQ + c + 1] = fmaxf(v1, 0.f);
        }
        __syncthreads();
    }
    if (tid < 16) {
        float s = 0.f;
        for (int c = 0; c < 64; c++) s = fmaf(t2b[tid * PQ + c], __ldg(&Wg2b[c]), s);
        z4v[tid] = s;
    }
    __syncthreads();
    if (tid < 16) {
        float s = 0.f;
        for (int q = 0; q < 16; q++) s = fmaf(__ldg(&g_An22[tid * 16 + q]), z4v[q], s);
        dout[b * 16 + tid] = s;
    }

    // -------- pairwise dist on xc (80x51) --------
    if (tid < 80) {
        float s = 0.f;
        for (int c = 0; c < 51; c++) {
            float v = xs[tid * PXM + c];
            s = fmaf(v, v, s);
        }
        sqv[tid] = s;
    }
    __syncthreads();
    {
        float acc[5][5];
        #pragma unroll
        for (int i = 0; i < 5; i++)
            #pragma unroll
            for (int j = 0; j < 5; j++) acc[i][j] = 0.f;
        for (int k = 0; k < 51; k++) {
            float a[5], bb[5];
            #pragma unroll
            for (int i = 0; i < 5; i++) a[i] = xs[(ty * 5 + i) * PXM + k];
            #pragma unroll
            for (int j = 0; j < 5; j++) bb[j] = xs[(tx * 5 + j) * PXM + k];
            #pragma unroll
            for (int i = 0; i < 5; i++)
                #pragma unroll
                for (int j = 0; j < 5; j++) acc[i][j] = fmaf(a[i], bb[j], acc[i][j]);
        }
        float* dd = dout + DIST_OFF + (size_t)b * 6400;
        #pragma unroll
        for (int i = 0; i < 5; i++)
            #pragma unroll
            for (int j = 0; j < 5; j++) {
                int n = ty * 5 + i, m = tx * 5 + j;
                float d2 = sqv[n] + sqv[m] - 2.f * acc[i][j];
                dd[n * 80 + m] = (d2 > 0.f) ? sqrtf(d2) : 0.f;
            }
    }
}

// =====================================================================
// launcher
// =====================================================================
extern "C" void kernel_launch(void* const* d_in, const int* in_sizes, int n_in,
                              void* d_out, int out_size)
{
    const float* data  = (const float*)d_in[0];
    const float* emb0  = (const float*)d_in[1];
    const float* emb1  = (const float*)d_in[2];
    const float* emb2  = (const float*)d_in[3];
    const float* w1    = (const float*)d_in[4];
    const float* b1    = (const float*)d_in[5];
    const float* w2    = (const float*)d_in[6];
    const float* b2    = (const float*)d_in[7];
    const float* w3    = (const float*)d_in[8];
    const float* b3    = (const float*)d_in[9];
    const float* M     = (const float*)d_in[10];
    const float* Wg1a  = (const float*)d_in[11];
    const float* Wg1b  = (const float*)d_in[12];
    const float* Wk    = (const float*)d_in[13];
    const float* smoothing = (const float*)d_in[14];
    const float* Wg2a  = (const float*)d_in[15];
    const float* Wg2b  = (const float*)d_in[16];
    float* out = (float*)d_out;

    const int SMEM_MLP  = (128 * PT + 64) * 4;
    const int SMEM_MAIN = (80 * PXM + 2 * 64 * PZB + 3 * 16 * PQ + 16 + 16 + 80) * 4;

    cudaFuncSetAttribute(k_mlp, cudaFuncAttributeMaxDynamicSharedMemorySize, SMEM_MLP);
    cudaFuncSetAttribute(k_main, cudaFuncAttributeMaxDynamicSharedMemorySize, SMEM_MAIN);

    k_mlp<<<1281, 256, SMEM_MLP>>>(data, emb0, emb1, emb2, w1, b1, w2, b2, w3, b3,
                                   M, Wk, smoothing, Wg1a, Wg1b, Wg2a, out + A_OFF);
    k_main<<<1024, 256, SMEM_MAIN>>>(Wg2b, out);
}

// round 7
// speedup vs baseline: 1.7408x; 1.0520x over previous
#include <cuda_runtime.h>
#include <math.h>

// ---------------- problem constants ----------------
#define BB    1024
#define NN_   80
#define CC    51     // OUTP
#define DM_   26
#define NEGV  -1e30f

#define DIST_OFF 16384
#define A_OFF    (16384 + 1024*6400)

typedef unsigned long long u64;

// ---------------- f32x2 packed helpers ----------------
__device__ __forceinline__ u64 pk2(float lo, float hi) {
    u64 r; asm("mov.b64 %0,{%1,%2};" : "=l"(r) : "f"(lo), "f"(hi)); return r;
}
__device__ __forceinline__ u64 dup2(float v) { return pk2(v, v); }
__device__ __forceinline__ void up2(u64 v, float& a, float& b) {
    asm("mov.b64 {%0,%1},%2;" : "=f"(a), "=f"(b) : "l"(v));
}
__device__ __forceinline__ u64 fma2(u64 a, u64 b, u64 c) {
    u64 d; asm("fma.rn.f32x2 %0,%1,%2,%3;" : "=l"(d) : "l"(a), "l"(b), "l"(c)); return d;
}

// ---------------- device scratch / prepped constants ----------------
__device__ float g_x[BB * NN_ * CC];
__device__ float g_An11[64 * 64];
__device__ float g_An22[16 * 16];
__device__ unsigned int g_AtmBits[32];
__device__ float g_Wg1aT[52 * 64];   // [k][o], row 51 zero
__device__ float g_Wg2aT[51 * 64];   // [k][o]
__device__ float g_Wg1bT[64 * 64];   // [h][o2], o2>=50 zero
__device__ float g_thetaB[52 * 64];  // [c][r], r>=50 zero, rows 50,51 zero
__device__ float g_coef;

// =====================================================================
// setup work: executed by one extra block of k_mlp (256 threads)
// =====================================================================
__device__ void do_setup(float* sh,
                         const float* __restrict__ M, const float* __restrict__ Wk,
                         const float* __restrict__ smoothing,
                         const float* __restrict__ Wg1a, const float* __restrict__ Wg1b,
                         const float* __restrict__ Wg2a,
                         float* __restrict__ outA)
{
    float* sM = sh;                 // 80*26
    float* sA = sM + NN_ * DM_;     // 80*80
    float* d1 = sA + NN_ * NN_;     // 64
    float* d2 = d1 + 64;            // 16
    const int tid = threadIdx.x;
    const int lane = tid & 31, warp = tid >> 5;

    for (int e = tid; e < NN_ * DM_; e += 256) sM[e] = M[e];
    for (int e = tid; e < NN_ * NN_; e += 256) sA[e] = 0.f;
    __syncthreads();

    for (int p = warp; p < NN_; p += 8) {
        float vals[3];
        float mx = NEGV;
        int cnt = 0;
        for (int q = lane; q < p; q += 32) {
            float s = 0.f;
            #pragma unroll
            for (int k = 0; k < DM_; k++) s = fmaf(sM[p * DM_ + k], sM[q * DM_ + k], s);
            s = fmaxf(s, 0.f);
            vals[cnt++] = s;
            mx = fmaxf(mx, s);
        }
        #pragma unroll
        for (int off = 16; off; off >>= 1) mx = fmaxf(mx, __shfl_xor_sync(0xffffffffu, mx, off));
        float sum = 0.f;
        for (int c = 0; c < cnt; c++) { vals[c] = expf(vals[c] - mx); sum += vals[c]; }
        #pragma unroll
        for (int off = 16; off; off >>= 1) sum += __shfl_xor_sync(0xffffffffu, sum, off);
        float inv = (p > 0) ? 1.f / sum : 0.f;
        cnt = 0;
        for (int q = lane; q < p; q += 32) sA[p * NN_ + q] = vals[cnt++] * inv;
    }
    __syncthreads();

    for (int e = tid; e < NN_ * NN_; e += 256) outA[e] = sA[e];

    if (tid < 64) {
        int c = 0;
        for (int q = 0; q < 64; q++) c += (sA[tid * NN_ + q] > 1e-15f) ? 1 : 0;
        d1[tid] = rsqrtf(1.f + (float)c);
    } else if (tid < 80) {
        int p = tid;
        int c = 0;
        for (int q = 64; q < 80; q++) c += (sA[p * NN_ + q] > 1e-15f) ? 1 : 0;
        d2[tid - 64] = rsqrtf(1.f + (float)c);
    }
    __syncthreads();

    for (int e = tid; e < 64 * 64; e += 256) {
        int p = e >> 6, q = e & 63;
        g_An11[e] = d1[p] * sA[p * NN_ + q] * d1[q];
    }
    if (tid < 256) {
        int p = tid >> 4, q = tid & 15;
        g_An22[tid] = d2[p] * sA[(64 + p) * NN_ + 64 + q] * d2[q];
    }

    if (tid < 16) {
        int p = 64 + tid;
        float mx = NEGV;
        for (int i = 0; i < 64; i++) {
            float a = sA[p * NN_ + i];
            mx = fmaxf(mx, (a != 0.f) ? a : NEGV);
        }
        float sum = 0.f;
        for (int i = 0; i < 64; i++) {
            float a = sA[p * NN_ + i];
            sum += expf(((a != 0.f) ? a : NEGV) - mx);
        }
        float inv = 1.f / sum;
        unsigned int b0 = 0u, b1 = 0u;
        for (int i = 0; i < 64; i++) {
            float a = sA[p * NN_ + i];
            float v = expf(((a != 0.f) ? a : NEGV) - mx) * inv;
            if (v >= 0.004f) {
                if (i < 32) b0 |= (1u << i);
                else        b1 |= (1u << (i - 32));
            }
        }
        g_AtmBits[tid * 2]     = b0;
        g_AtmBits[tid * 2 + 1] = b1;
    }

    // theta (padded): rows >=50 zero, cols r>=50 zero
    for (int e = tid; e < 52 * 64; e += 256) {
        int c = e >> 6, r = e & 63;
        float s = 0.f;
        if (c < 50 && r < 50) {
            #pragma unroll 8
            for (int k = 0; k < 64; k++) s = fmaf(Wk[c * 64 + k], Wk[r * 64 + k], s);
        }
        g_thetaB[e] = s;
    }

    // transposed weights (g_Wg1aT padded to 52 rows, row 51 zero)
    for (int e = tid; e < 52 * 64; e += 256) {
        int k = e >> 6, o = e & 63;
        g_Wg1aT[e] = (k < 51) ? Wg1a[o * 51 + k] : 0.f;
    }
    for (int e = tid; e < 51 * 64; e += 256) {
        int k = e >> 6, o = e & 63;
        g_Wg2aT[e] = Wg2a[o * 51 + k];
    }
    for (int e = tid; e < 64 * 64; e += 256) {
        int h = e >> 6, o = e & 63;
        g_Wg1bT[e] = (o < 50) ? Wg1b[o * 64 + h] : 0.f;
    }

    if (tid == 0) {
        float sg = 1.f / (1.f + expf(-smoothing[0]));
        g_coef = -0.5f / (sg * 0.01f);
    }
}

// =====================================================================
// Kernel 1: gather + 3-layer MLP. Feature-major token buffer (in-place),
// w1 staged in smem (padded K=52), w2/w3 as global float4 A-prefetch.
// =====================================================================
#define PT  68   // token buffer pitch (mult of 4)
#define PW1 52   // staged w1 pitch (mult of 4)

__global__ void __launch_bounds__(256, 3) k_mlp(
    const float* __restrict__ data,
    const float* __restrict__ emb0, const float* __restrict__ emb1, const float* __restrict__ emb2,
    const float* __restrict__ w1, const float* __restrict__ b1,
    const float* __restrict__ w2, const float* __restrict__ b2,
    const float* __restrict__ w3, const float* __restrict__ b3,
    const float* __restrict__ M, const float* __restrict__ Wk,
    const float* __restrict__ smoothing,
    const float* __restrict__ Wg1a, const float* __restrict__ Wg1b,
    const float* __restrict__ Wg2a,
    float* __restrict__ outA)
{
    extern __shared__ float sh[];

    if (blockIdx.x == 1280) {
        do_setup(sh, M, Wk, smoothing, Wg1a, Wg1b, Wg2a, outA);
        return;
    }

    float* T     = sh;               // 128 * PT (feature-major: [feat][token])
    float* w1s   = T + 128 * PT;     // 128 * PW1
    float* sLast = w1s + 128 * PW1;  // 64

    const int tid = threadIdx.x;
    const int cx = tid & 15, ry = tid >> 4;
    const int base = blockIdx.x * 64;

    if (tid < 64) sLast[tid] = data[(size_t)(base + tid) * 6 + 5];

    // stage w1 (128 x 51 -> pitch 52, col 51 zero)
    for (int e = tid; e < 128 * PW1; e += 256) {
        int o = e / PW1, k = e % PW1;
        w1s[e] = (k < 51) ? w1[o * 51 + k] : 0.f;
    }
    // gather X^T (52 x 64): T[c][t], row 51 zero
    for (int e = tid; e < 52 * 64; e += 256) {
        int c = e >> 6, t = e & 63;
        const float* dr = data + (size_t)(base + t) * 6;
        float v;
        if (c < 32)      { int i0 = (int)dr[0]; v = emb0[i0 * 32 + c]; }
        else if (c < 40) { int i1 = (int)dr[1]; v = emb1[i1 * 8 + (c - 32)]; }
        else if (c < 48) { int i2 = (int)dr[2]; v = emb2[i2 * 8 + (c - 40)]; }
        else if (c < 51) { v = dr[3 + (c - 48)]; }
        else             { v = 0.f; }
        T[c * PT + t] = v;
    }
    __syncthreads();

    // ---- GEMM1: h1[o][t] = relu(sum_k w1s[o][k]*T[k][t] + b1[o]), K=52 ----
    {
        u64 acc[8][2];
        #pragma unroll
        for (int i = 0; i < 8; i++) { acc[i][0] = 0ull; acc[i][1] = 0ull; }
        for (int k0 = 0; k0 < 52; k0 += 4) {
            float4 ap[8];
            #pragma unroll
            for (int i = 0; i < 8; i++)
                ap[i] = *reinterpret_cast<const float4*>(&w1s[(ry + 16 * i) * PW1 + k0]);
            #pragma unroll
            for (int kk = 0; kk < 4; kk++) {
                ulonglong2 bv = *reinterpret_cast<const ulonglong2*>(&T[(k0 + kk) * PT + 4 * cx]);
                #pragma unroll
                for (int i = 0; i < 8; i++) {
                    float av = (kk == 0) ? ap[i].x : (kk == 1) ? ap[i].y : (kk == 2) ? ap[i].z : ap[i].w;
                    u64 ad = dup2(av);
                    acc[i][0] = fma2(ad, bv.x, acc[i][0]);
                    acc[i][1] = fma2(ad, bv.y, acc[i][1]);
                }
            }
        }
        __syncthreads();
        #pragma unroll
        for (int i = 0; i < 8; i++) {
            int o = ry + 16 * i;
            float bo = __ldg(&b1[o]);
            float4 v;
            up2(acc[i][0], v.x, v.y);
            up2(acc[i][1], v.z, v.w);
            v.x = fmaxf(v.x + bo, 0.f); v.y = fmaxf(v.y + bo, 0.f);
            v.z = fmaxf(v.z + bo, 0.f); v.w = fmaxf(v.w + bo, 0.f);
            *reinterpret_cast<float4*>(&T[o * PT + 4 * cx]) = v;
        }
        __syncthreads();
    }

    // ---- GEMM2: h2 = relu(w2 @ T + b2), K=128 ----
    {
        u64 acc[8][2];
        #pragma unroll
        for (int i = 0; i < 8; i++) { acc[i][0] = 0ull; acc[i][1] = 0ull; }
        #pragma unroll 2
        for (int k0 = 0; k0 < 128; k0 += 4) {
            float4 ap[8];
            #pragma unroll
            for (int i = 0; i < 8; i++)
                ap[i] = *reinterpret_cast<const float4*>(&w2[(ry + 16 * i) * 128 + k0]);
            #pragma unroll
            for (int kk = 0; kk < 4; kk++) {
                ulonglong2 bv = *reinterpret_cast<const ulonglong2*>(&T[(k0 + kk) * PT + 4 * cx]);
                #pragma unroll
                for (int i = 0; i < 8; i++) {
                    float av = (kk == 0) ? ap[i].x : (kk == 1) ? ap[i].y : (kk == 2) ? ap[i].z : ap[i].w;
                    u64 ad = dup2(av);
                    acc[i][0] = fma2(ad, bv.x, acc[i][0]);
                    acc[i][1] = fma2(ad, bv.y, acc[i][1]);
                }
            }
        }
        __syncthreads();
        #pragma unroll
        for (int i = 0; i < 8; i++) {
            int o = ry + 16 * i;
            float bo = __ldg(&b2[o]);
            float4 v;
            up2(acc[i][0], v.x, v.y);
            up2(acc[i][1], v.z, v.w);
            v.x = fmaxf(v.x + bo, 0.f); v.y = fmaxf(v.y + bo, 0.f);
            v.z = fmaxf(v.z + bo, 0.f); v.w = fmaxf(v.w + bo, 0.f);
            *reinterpret_cast<float4*>(&T[o * PT + 4 * cx]) = v;
        }
        __syncthreads();
    }

    // ---- GEMM3: h3 = w3 @ T + b3 (o<50) -> g_x, K=128 ----
    {
        u64 acc[4][2];
        #pragma unroll
        for (int i = 0; i < 4; i++) { acc[i][0] = 0ull; acc[i][1] = 0ull; }
        #pragma unroll 2
        for (int k0 = 0; k0 < 128; k0 += 4) {
            float4 ap[4];
            #pragma unroll
            for (int i = 0; i < 4; i++) {
                int o = ry + 16 * i;
                ap[i] = (o < 50) ? *reinterpret_cast<const float4*>(&w3[o * 128 + k0])
                                 : make_float4(0.f, 0.f, 0.f, 0.f);
            }
            #pragma unroll
            for (int kk = 0; kk < 4; kk++) {
                ulonglong2 bv = *reinterpret_cast<const ulonglong2*>(&T[(k0 + kk) * PT + 4 * cx]);
                #pragma unroll
                for (int i = 0; i < 4; i++) {
                    float av = (kk == 0) ? ap[i].x : (kk == 1) ? ap[i].y : (kk == 2) ? ap[i].z : ap[i].w;
                    u64 ad = dup2(av);
                    acc[i][0] = fma2(ad, bv.x, acc[i][0]);
                    acc[i][1] = fma2(ad, bv.y, acc[i][1]);
                }
            }
        }
        #pragma unroll
        for (int i = 0; i < 4; i++) {
            int o = ry + 16 * i;
            if (o < 50) {
                float bo = __ldg(&b3[o]);
                float v0, v1, v2, v3;
                up2(acc[i][0], v0, v1);
                up2(acc[i][1], v2, v3);
                int t = base + 4 * cx;
                g_x[(size_t)(t + 0) * CC + o] = v0 + bo;
                g_x[(size_t)(t + 1) * CC + o] = v1 + bo;
                g_x[(size_t)(t + 2) * CC + o] = v2 + bo;
                g_x[(size_t)(t + 3) * CC + o] = v3 + bo;
            }
        }
        if (tid < 64) g_x[(size_t)(base + tid) * CC + 50] = sLast[tid];
    }
}

// =====================================================================
// Kernel 2: per-graph pipeline. float4 A-operands, K mult-of-4.
// =====================================================================
#define PXM 52   // xs pitch (mult of 4; rows 16B aligned: 52*4=208)
#define PZB 68   // big buffer pitch (mult of 4; 68*4=272 -> 16B aligned)
#define PQ  66   // small 16-row buffer pitch (even)

// C(64x64) = A(64xK smem, pitch pa mult4) @ B(Kx64 global, ld 64). K mult of 4.
// C may alias A (full read before sync).
__device__ __forceinline__ void gemm_AS_BG(const float* As, int pa,
                                           const float* __restrict__ Bg, int K,
                                           float* Cs, bool do_relu, int cx, int ry)
{
    u64 acc[4][2];
    #pragma unroll
    for (int i = 0; i < 4; i++) { acc[i][0] = 0ull; acc[i][1] = 0ull; }
    for (int k0 = 0; k0 < K; k0 += 4) {
        float4 ap[4];
        #pragma unroll
        for (int i = 0; i < 4; i++)
            ap[i] = *reinterpret_cast<const float4*>(As + (ry + 16 * i) * pa + k0);
        #pragma unroll
        for (int kk = 0; kk < 4; kk++) {
            ulonglong2 bv = *reinterpret_cast<const ulonglong2*>(Bg + (k0 + kk) * 64 + 4 * cx);
            #pragma unroll
            for (int i = 0; i < 4; i++) {
                float av = (kk == 0) ? ap[i].x : (kk == 1) ? ap[i].y : (kk == 2) ? ap[i].z : ap[i].w;
                u64 ad = dup2(av);
                acc[i][0] = fma2(ad, bv.x, acc[i][0]);
                acc[i][1] = fma2(ad, bv.y, acc[i][1]);
            }
        }
    }
    __syncthreads();
    #pragma unroll
    for (int i = 0; i < 4; i++) {
        float4 v;
        up2(acc[i][0], v.x, v.y);
        up2(acc[i][1], v.z, v.w);
        if (do_relu) {
            v.x = fmaxf(v.x, 0.f); v.y = fmaxf(v.y, 0.f);
            v.z = fmaxf(v.z, 0.f); v.w = fmaxf(v.w, 0.f);
        }
        *reinterpret_cast<float4*>(&Cs[(ry + 16 * i) * PZB + 4 * cx]) = v;
    }
    __syncthreads();
}

// C(64x64) = A(64x64 global, ld 64) @ B(64x64 smem, pitch PZB). C may alias B.
__device__ __forceinline__ void gemm_AG_BS(const float* __restrict__ Ag,
                                           const float* Bs,
                                           float* Cs, bool do_relu, int cx, int ry)
{
    u64 acc[4][2];
    #pragma unroll
    for (int i = 0; i < 4; i++) { acc[i][0] = 0ull; acc[i][1] = 0ull; }
    for (int k0 = 0; k0 < 64; k0 += 4) {
        float4 ap[4];
        #pragma unroll
        for (int i = 0; i < 4; i++)
            ap[i] = *reinterpret_cast<const float4*>(Ag + (ry + 16 * i) * 64 + k0);
        #pragma unroll
        for (int kk = 0; kk < 4; kk++) {
            ulonglong2 bv = *reinterpret_cast<const ulonglong2*>(&Bs[(k0 + kk) * PZB + 4 * cx]);
            #pragma unroll
            for (int i = 0; i < 4; i++) {
                float av = (kk == 0) ? ap[i].x : (kk == 1) ? ap[i].y : (kk == 2) ? ap[i].z : ap[i].w;
                u64 ad = dup2(av);
                acc[i][0] = fma2(ad, bv.x, acc[i][0]);
                acc[i][1] = fma2(ad, bv.y, acc[i][1]);
            }
        }
    }
    __syncthreads();
    #pragma unroll
    for (int i = 0; i < 4; i++) {
        float4 v;
        up2(acc[i][0], v.x, v.y);
        up2(acc[i][1], v.z, v.w);
        if (do_relu) {
            v.x = fmaxf(v.x, 0.f); v.y = fmaxf(v.y, 0.f);
            v.z = fmaxf(v.z, 0.f); v.w = fmaxf(v.w, 0.f);
        }
        *reinterpret_cast<float4*>(&Cs[(ry + 16 * i) * PZB + 4 * cx]) = v;
    }
    __syncthreads();
}

__global__ void __launch_bounds__(256, 3) k_main(
    const float* __restrict__ Wg2b,
    float* __restrict__ dout)
{
    extern __shared__ float sh[];
    float* xs  = sh;                 // 80*PXM
    float* B1  = xs + 80 * PXM;      // 64*PZB
    float* B2  = B1 + 64 * PZB;      // 64*PZB
    float* z3  = B2 + 64 * PZB;      // 16*PQ
    float* t2b = z3 + 16 * PQ;       // 16*PQ
    float* Ls  = t2b + 16 * PQ;      // 16*PQ
    float* yhv = Ls + 16 * PQ;       // 16
    float* z4v = yhv + 16;           // 16
    float* sqv = z4v + 16;           // 80

    const int tid = threadIdx.x;
    const int tx = tid & 15, ty = tid >> 4;
    const int b = blockIdx.x;
    const float* gx = g_x + (size_t)b * NN_ * CC;

    // -------- load per-graph features (pitch 52, col 51 zero) --------
    for (int e = tid; e < 80 * PXM; e += 256) {
        int r = e / PXM, c = e % PXM;
        xs[e] = (c < 51) ? gx[r * 51 + c] : 0.f;
    }
    __syncthreads();

    // -------- gcnn1 chain --------
    gemm_AS_BG(xs, PXM, g_Wg1aT, 52, B1, false, tx, ty);   // z1
    gemm_AG_BS(g_An11, B1, B1, true, tx, ty);              // t1 = relu(An11 @ z1)
    gemm_AS_BG(B1, PZB, g_Wg1bT, 64, B1, false, tx, ty);   // z2
    gemm_AG_BS(g_An11, B1, B2, false, tx, ty);             // x1 -> B2
    gemm_AS_BG(B2, PZB, g_thetaB, 52, B1, false, tx, ty);  // u  -> B1

    // -------- v = xf @ theta (16x64) -> z3, K=50 float2 --------
    {
        u64 acc[2] = {0ull, 0ull};
        for (int k = 0; k < 50; k += 2) {
            float2 a = *reinterpret_cast<const float2*>(&xs[(64 + ty) * PXM + k]);
            u64 a0 = dup2(a.x), a1 = dup2(a.y);
            acc[0] = fma2(a0, *reinterpret_cast<const u64*>(&g_thetaB[k * 64 + 2 * tx]), acc[0]);
            acc[1] = fma2(a0, *reinterpret_cast<const u64*>(&g_thetaB[k * 64 + 2 * tx + 32]), acc[1]);
            acc[0] = fma2(a1, *reinterpret_cast<const u64*>(&g_thetaB[(k + 1) * 64 + 2 * tx]), acc[0]);
            acc[1] = fma2(a1, *reinterpret_cast<const u64*>(&g_thetaB[(k + 1) * 64 + 2 * tx + 32]), acc[1]);
        }
        __syncthreads();
        #pragma unroll
        for (int j = 0; j < 2; j++) {
            float v0, v1; up2(acc[j], v0, v1);
            int c = 2 * tx + 32 * j;
            z3[ty * PQ + c] = v0;
            z3[ty * PQ + c + 1] = v1;
        }
        __syncthreads();
    }

    // -------- q[j][i] = (xp_i - xf_j).(u_i - v_j), K=50 float2 --------
    {
        float cf = g_coef;
        float acc[4] = {0.f, 0.f, 0.f, 0.f};
        for (int k = 0; k < 50; k += 2) {
            float2 xf2 = *reinterpret_cast<const float2*>(&xs[(64 + ty) * PXM + k]);
            float2 v2  = *reinterpret_cast<const float2*>(&z3[ty * PQ + k]);
            #pragma unroll
            for (int j = 0; j < 4; j++) {
                int i = tx + 16 * j;
                float2 b2v = *reinterpret_cast<const float2*>(&B2[i * PZB + k]);
                float2 b1v = *reinterpret_cast<const float2*>(&B1[i * PZB + k]);
                acc[j] = fmaf(b2v.x - xf2.x, b1v.x - v2.x, acc[j]);
                acc[j] = fmaf(b2v.y - xf2.y, b1v.y - v2.y, acc[j]);
            }
        }
        unsigned int m0 = __ldg(&g_AtmBits[ty * 2]);
        unsigned int m1 = __ldg(&g_AtmBits[ty * 2 + 1]);
        __syncthreads();
        #pragma unroll
        for (int j = 0; j < 4; j++) {
            int i = tx + 16 * j;
            bool on = (i < 32) ? ((m0 >> i) & 1u) : ((m1 >> (i - 32)) & 1u);
            Ls[ty * PQ + i] = on ? (cf * acc[j]) : NEGV;
        }
        __syncthreads();
    }

    // -------- softmax over j --------
    if (tid < 64) {
        int i = tid;
        float m = NEGV;
        for (int j = 0; j < 16; j++) m = fmaxf(m, Ls[j * PQ + i]);
        float s = 0.f;
        for (int j = 0; j < 16; j++) {
            float e = expf(Ls[j * PQ + i] - m);
            Ls[j * PQ + i] = e;
            s += e;
        }
        float inv = 1.f / s;
        for (int j = 0; j < 16; j++) Ls[j * PQ + i] *= inv;
    }
    __syncthreads();

    // -------- yh, splice --------
    if (tid < 16) {
        float s = 0.f;
        for (int i = 0; i < 64; i++) s = fmaf(Ls[tid * PQ + i], xs[i * PXM + 50], s);
        yhv[tid] = s;
    }
    __syncthreads();
    if (tid < 16) xs[(64 + tid) * PXM + 50] = yhv[tid];
    __syncthreads();

    // -------- gcnn2: z3g = x2 @ Wg2a^T, K=51 (float2 + tail) --------
    {
        u64 acc[2] = {0ull, 0ull};
        for (int k = 0; k < 50; k += 2) {
            float2 a = *reinterpret_cast<const float2*>(&xs[(64 + ty) * PXM + k]);
            u64 a0 = dup2(a.x), a1 = dup2(a.y);
            acc[0] = fma2(a0, *reinterpret_cast<const u64*>(&g_Wg2aT[k * 64 + 2 * tx]), acc[0]);
            acc[1] = fma2(a0, *reinterpret_cast<const u64*>(&g_Wg2aT[k * 64 + 2 * tx + 32]), acc[1]);
            acc[0] = fma2(a1, *reinterpret_cast<const u64*>(&g_Wg2aT[(k + 1) * 64 + 2 * tx]), acc[0]);
            acc[1] = fma2(a1, *reinterpret_cast<const u64*>(&g_Wg2aT[(k + 1) * 64 + 2 * tx + 32]), acc[1]);
        }
        { // k = 50
            u64 a0 = dup2(xs[(64 + ty) * PXM + 50]);
            acc[0] = fma2(a0, *reinterpret_cast<const u64*>(&g_Wg2aT[50 * 64 + 2 * tx]), acc[0]);
            acc[1] = fma2(a0, *reinterpret_cast<const u64*>(&g_Wg2aT[50 * 64 + 2 * tx + 32]), acc[1]);
        }
        __syncthreads();
        #pragma unroll
        for (int j = 0; j < 2; j++) {
            float v0, v1; up2(acc[j], v0, v1);
            int c = 2 * tx + 32 * j;
            z3[ty * PQ + c] = v0;
            z3[ty * PQ + c + 1] = v1;
        }
        __syncthreads();
    }
    {   // t2 = relu(An22 @ z3g)
        u64 acc[2] = {0ull, 0ull};
        for (int q = 0; q < 16; q++) {
            u64 ad = dup2(__ldg(&g_An22[ty * 16 + q]));
            acc[0] = fma2(ad, *reinterpret_cast<const u64*>(&z3[q * PQ + 2 * tx]), acc[0]);
            acc[1] = fma2(ad, *reinterpret_cast<const u64*>(&z3[q * PQ + 2 * tx + 32]), acc[1]);
        }
        __syncthreads();
        #pragma unroll
        for (int j = 0; j < 2; j++) {
            float v0, v1; up2(acc[j], v0, v1);
            int c = 2 * tx + 32 * j;
            t2b[ty * PQ + c]     = fmaxf(v0, 0.f);
            t2b[ty * PQ + c + 1] = fmaxf(v1, 0.f);
        }
        __syncthreads();
    }
    if (tid < 16) {
        float s = 0.f;
        for (int c = 0; c < 64; c++) s = fmaf(t2b[tid * PQ + c], __ldg(&Wg2b[c]), s);
        z4v[tid] = s;
    }
    __syncthreads();
    if (tid < 16) {
        float s = 0.f;
        for (int q = 0; q < 16; q++) s = fmaf(__ldg(&g_An22[tid * 16 + q]), z4v[q], s);
        dout[b * 16 + tid] = s;
    }

    // -------- pairwise dist on xc (80x52, col 51 zero) --------
    if (tid < 80) {
        float s = 0.f;
        for (int c = 0; c < 51; c++) {
            float v = xs[tid * PXM + c];
            s = fmaf(v, v, s);
        }
        sqv[tid] = s;
    }
    __syncthreads();
    {
        float acc[5][5];
        #pragma unroll
        for (int i = 0; i < 5; i++)
            #pragma unroll
            for (int j = 0; j < 5; j++) acc[i][j] = 0.f;
        for (int k0 = 0; k0 < 52; k0 += 4) {
            float4 a4[5], b4[5];
            #pragma unroll
            for (int i = 0; i < 5; i++)
                a4[i] = *reinterpret_cast<const float4*>(&xs[(ty * 5 + i) * PXM + k0]);
            #pragma unroll
            for (int j = 0; j < 5; j++)
                b4[j] = *reinterpret_cast<const float4*>(&xs[(tx * 5 + j) * PXM + k0]);
            #pragma unroll
            for (int i = 0; i < 5; i++)
                #pragma unroll
                for (int j = 0; j < 5; j++) {
                    acc[i][j] = fmaf(a4[i].x, b4[j].x, acc[i][j]);
                    acc[i][j] = fmaf(a4[i].y, b4[j].y, acc[i][j]);
                    acc[i][j] = fmaf(a4[i].z, b4[j].z, acc[i][j]);
                    acc[i][j] = fmaf(a4[i].w, b4[j].w, acc[i][j]);
                }
        }
        float* dd = dout + DIST_OFF + (size_t)b * 6400;
        #pragma unroll
        for (int i = 0; i < 5; i++)
            #pragma unroll
            for (int j = 0; j < 5; j++) {
                int n = ty * 5 + i, m = tx * 5 + j;
                float d2 = sqv[n] + sqv[m] - 2.f * acc[i][j];
                dd[n * 80 + m] = (d2 > 0.f) ? sqrtf(d2) : 0.f;
            }
    }
}

// =====================================================================
// launcher
// =====================================================================
extern "C" void kernel_launch(void* const* d_in, const int* in_sizes, int n_in,
                              void* d_out, int out_size)
{
    const float* data  = (const float*)d_in[0];
    const float* emb0  = (const float*)d_in[1];
    const float* emb1  = (const float*)d_in[2];
    const float* emb2  = (const float*)d_in[3];
    const float* w1    = (const float*)d_in[4];
    const float* b1    = (const float*)d_in[5];
    const float* w2    = (const float*)d_in[6];
    const float* b2    = (const float*)d_in[7];
    const float* w3    = (const float*)d_in[8];
    const float* b3    = (const float*)d_in[9];
    const float* M     = (const float*)d_in[10];
    const float* Wg1a  = (const float*)d_in[11];
    const float* Wg1b  = (const float*)d_in[12];
    const float* Wk    = (const float*)d_in[13];
    const float* smoothing = (const float*)d_in[14];
    const float* Wg2a  = (const float*)d_in[15];
    const float* Wg2b  = (const float*)d_in[16];
    float* out = (float*)d_out;

    const int SMEM_MLP  = (128 * PT + 128 * PW1 + 64) * 4;
    const int SMEM_MAIN = (80 * PXM + 2 * 64 * PZB + 3 * 16 * PQ + 16 + 16 + 80) * 4;

    cudaFuncSetAttribute(k_mlp, cudaFuncAttributeMaxDynamicSharedMemorySize, SMEM_MLP);
    cudaFuncSetAttribute(k_main, cudaFuncAttributeMaxDynamicSharedMemorySize, SMEM_MAIN);

    k_mlp<<<1281, 256, SMEM_MLP>>>(data, emb0, emb1, emb2, w1, b1, w2, b2, w3, b3,
                                   M, Wk, smoothing, Wg1a, Wg1b, Wg2a, out + A_OFF);
    k_main<<<1024, 256, SMEM_MAIN>>>(Wg2b, out);
}